// round 8
// baseline (speedup 1.0000x reference)
#include <cuda_runtime.h>
#include <cuda_fp16.h>
#include <math.h>

#define NN 50000
#define NE 1600000
#define DD 128
#define HH 8
#define NPART 8
#define NSLOT 256
#define GEMMB 391            // (NN+127)/128

// ---------------- scratch (no allocations allowed) ----------------
__device__ __half2 g_xlh[NN * 64];     // x @ W in fp16
__device__ float  g_h[NN * DD];        // pre-BN output
__device__ float  g_asrc[NN * HH];
__device__ float  g_adst[NN * HH];
__device__ int    g_deg[NPART * NN];   // zeroed by previous call's k_final (zero-init at load)
__device__ int    g_cur[NPART * NN];
__device__ int    g_rank[NE];
__device__ int    g_rowptr[NN + 1];
__device__ int    g_csrc[NE];
__device__ float  g_ps1[NSLOT * 128];  // BN partials (zeroed by previous k_final)
__device__ float  g_ps2[NSLOT * 128];
__device__ float  g_scale[DD];
__device__ float  g_shift[DD];
__device__ int    g_is64 = -1;         // -1 = unknown (first call self-detects)

// ---------------- f32x2 helpers ----------------
#define FMA2(d, a, b, c) \
    asm("fma.rn.f32x2 %0, %1, %2, %3;" : "=l"(d) : "l"(a), "l"(b), "l"(c))

__device__ __forceinline__ unsigned long long pk2(float v) {
    unsigned long long r;
    unsigned int u = __float_as_uint(v);
    asm("mov.b64 %0, {%1, %2};" : "=l"(r) : "r"(u), "r"(u));
    return r;
}
__device__ __forceinline__ void upk2(unsigned long long v, float& lo, float& hi) {
    unsigned int a, b;
    asm("mov.b64 {%0, %1}, %2;" : "=r"(a), "=r"(b) : "l"(v));
    lo = __uint_as_float(a);
    hi = __uint_as_float(b);
}

__device__ __forceinline__ int detect64(const unsigned int* w) {
    int is64 = 1;
    for (int j = 1; j < 64; j += 2)
        if (w[j] != 0u) { is64 = 0; break; }
    return is64;
}

__device__ __forceinline__ int edge_val(const void* ei, long long flat, int is64) {
    if (is64) return (int)((const long long*)ei)[flat];
    return ((const int*)ei)[flat];
}

// ================= fused kernel: gemm (blocks 0..390) + hist (rest) =================
__global__ __launch_bounds__(256, 2) void k_fuse(const float* __restrict__ x,
                                                 const float* __restrict__ W,
                                                 const float* __restrict__ att_src,
                                                 const float* __restrict__ att_dst,
                                                 const void* __restrict__ ei) {
    __shared__ float xs[32][136];   // [k][row], padded
    __shared__ float ws[32][132];   // [k][col], padded
    int tid = threadIdx.x;

    if (blockIdx.x >= GEMMB) {
        // -------- hist: rank recording + 8-way partial histograms --------
        int e = (blockIdx.x - GEMMB) * 256 + tid;
        if (e >= NE) return;
        int is64 = g_is64;
        if (is64 < 0) is64 = detect64((const unsigned int*)ei);   // call-1 self-detect
        int dst = edge_val(ei, (long long)NE + e, is64);
        int part = e & (NPART - 1);
        g_rank[e] = atomicAdd(&g_deg[part * NN + dst], 1);
        return;
    }

    // -------- gemm: 128x128 block tile, 16x4 thread tile, f32x2 --------
    int lane = tid & 31;
    int row0 = blockIdx.x * 128;
    int r0 = (tid >> 5) * 16;
    int c0 = lane * 4;

    unsigned long long acc[16][2];
#pragma unroll
    for (int i = 0; i < 16; i++) { acc[i][0] = 0ull; acc[i][1] = 0ull; }

#pragma unroll 1
    for (int kk = 0; kk < 128; kk += 32) {
        {   // W tile: 32 k-rows x 128 cols
            int lk = tid >> 3;
            int lc = (tid & 7) * 16;
            const float4* wp = (const float4*)(W + (size_t)(kk + lk) * 128 + lc);
            float4* q = (float4*)&ws[lk][lc];
            q[0] = wp[0]; q[1] = wp[1]; q[2] = wp[2]; q[3] = wp[3];
        }
        {   // x tile: 128 rows x 32 k, stored transposed
            int lr = tid >> 1;
            int k0 = (tid & 1) * 16;
            int grow = row0 + lr; if (grow >= NN) grow = NN - 1;
            const float* xp = x + (size_t)grow * 128 + kk + k0;
            float4 a = *(const float4*)xp;
            float4 b = *(const float4*)(xp + 4);
            float4 c = *(const float4*)(xp + 8);
            float4 d = *(const float4*)(xp + 12);
            xs[k0 + 0][lr] = a.x;  xs[k0 + 1][lr] = a.y;
            xs[k0 + 2][lr] = a.z;  xs[k0 + 3][lr] = a.w;
            xs[k0 + 4][lr] = b.x;  xs[k0 + 5][lr] = b.y;
            xs[k0 + 6][lr] = b.z;  xs[k0 + 7][lr] = b.w;
            xs[k0 + 8][lr] = c.x;  xs[k0 + 9][lr] = c.y;
            xs[k0 + 10][lr] = c.z; xs[k0 + 11][lr] = c.w;
            xs[k0 + 12][lr] = d.x; xs[k0 + 13][lr] = d.y;
            xs[k0 + 14][lr] = d.z; xs[k0 + 15][lr] = d.w;
        }
        __syncthreads();
#pragma unroll 2
        for (int k = 0; k < 32; k++) {
            ulonglong2 wv = *(const ulonglong2*)&ws[k][c0];
            float4 xa = *(const float4*)&xs[k][r0];
            float4 xb = *(const float4*)&xs[k][r0 + 4];
            float4 xc = *(const float4*)&xs[k][r0 + 8];
            float4 xd = *(const float4*)&xs[k][r0 + 12];
            float xr[16] = {xa.x, xa.y, xa.z, xa.w, xb.x, xb.y, xb.z, xb.w,
                            xc.x, xc.y, xc.z, xc.w, xd.x, xd.y, xd.z, xd.w};
#pragma unroll
            for (int i = 0; i < 16; i++) {
                unsigned long long xp2 = pk2(xr[i]);
                FMA2(acc[i][0], xp2, wv.x, acc[i][0]);
                FMA2(acc[i][1], xp2, wv.y, acc[i][1]);
            }
        }
        __syncthreads();
    }

    // epilogue: fp16 xl + fused attention logits (fp32 accumulators)
    float4 asv = ((const float4*)att_src)[lane];
    float4 adv = ((const float4*)att_dst)[lane];
    int head = lane >> 2;
#pragma unroll
    for (int i = 0; i < 16; i++) {
        int r = row0 + r0 + i;
        float o0, o1, o2, o3;
        upk2(acc[i][0], o0, o1);
        upk2(acc[i][1], o2, o3);
        float ps = o0 * asv.x + o1 * asv.y + o2 * asv.z + o3 * asv.w;
        float pd = o0 * adv.x + o1 * adv.y + o2 * adv.z + o3 * adv.w;
        ps += __shfl_xor_sync(0xffffffffu, ps, 1);
        ps += __shfl_xor_sync(0xffffffffu, ps, 2);
        pd += __shfl_xor_sync(0xffffffffu, pd, 1);
        pd += __shfl_xor_sync(0xffffffffu, pd, 2);
        if (r < NN) {
            __half2 p0 = __float22half2_rn(make_float2(o0, o1));
            __half2 p1 = __float22half2_rn(make_float2(o2, o3));
            uint2 u;
            u.x = *(unsigned int*)&p0;
            u.y = *(unsigned int*)&p1;
            ((uint2*)g_xlh)[(size_t)r * 32 + lane] = u;
            if ((lane & 3) == 0) {
                g_asrc[r * 8 + head] = ps;
                g_adst[r * 8 + head] = pd;
            }
        }
    }
}

// ---------------- scan: rowptr + 8-way cursor bases ----------------
__global__ void k_scan() {
    __shared__ int warpsum[32];
    __shared__ int carry;
    int tid = threadIdx.x, lane = tid & 31, wid = tid >> 5;
    if (tid == 0) { carry = 0; g_rowptr[0] = 0; }
    __syncthreads();
    for (int base = 0; base < NN; base += 1024) {
        int i = base + tid;
        int d[NPART];
        int v = 0;
#pragma unroll
        for (int p = 0; p < NPART; p++) {
            d[p] = (i < NN) ? g_deg[p * NN + i] : 0;
            v += d[p];
        }
        int s = v;
#pragma unroll
        for (int off = 1; off < 32; off <<= 1) {
            int t = __shfl_up_sync(0xffffffffu, s, off);
            if (lane >= off) s += t;
        }
        if (lane == 31) warpsum[wid] = s;
        __syncthreads();
        if (wid == 0) {
            int ws = warpsum[lane];
            int ss = ws;
#pragma unroll
            for (int off = 1; off < 32; off <<= 1) {
                int t = __shfl_up_sync(0xffffffffu, ss, off);
                if (lane >= off) ss += t;
            }
            warpsum[lane] = ss - ws;
        }
        __syncthreads();
        int incl = s + warpsum[wid] + carry;
        if (i < NN) {
            g_rowptr[i + 1] = incl;
            int b = incl - v;
#pragma unroll
            for (int p = 0; p < NPART; p++) {
                g_cur[p * NN + i] = b;
                b += d[p];
            }
        }
        __syncthreads();
        if (tid == 1023) carry = incl;
        __syncthreads();
    }
}

// ---------------- fill: 4 edges/thread, no atomics ----------------
__global__ void k_fill(const void* __restrict__ ei) {
    int g = blockIdx.x * blockDim.x + threadIdx.x;   // NE/4 threads
    if (g >= NE / 4) return;
    int is64 = g_is64;            // set by k_fuse-call-1? no: set by prior final; call 1: detect here
    int e0 = g * 4;
    int src[4], dst[4], rk[4];
    if (is64 < 0) is64 = detect64((const unsigned int*)ei);
    if (is64) {
#pragma unroll
        for (int q = 0; q < 4; q++) {
            src[q] = edge_val(ei, e0 + q, 1);
            dst[q] = edge_val(ei, (long long)NE + e0 + q, 1);
        }
    } else {
        int4 s4 = ((const int4*)ei)[g];
        int4 d4 = ((const int4*)ei)[NE / 4 + g];
        src[0] = s4.x; src[1] = s4.y; src[2] = s4.z; src[3] = s4.w;
        dst[0] = d4.x; dst[1] = d4.y; dst[2] = d4.z; dst[3] = d4.w;
    }
    int4 r4 = ((const int4*)g_rank)[g];
    rk[0] = r4.x; rk[1] = r4.y; rk[2] = r4.z; rk[3] = r4.w;
    int pos[4];
#pragma unroll
    for (int q = 0; q < 4; q++) {
        int part = (e0 + q) & (NPART - 1);
        pos[q] = g_cur[part * NN + dst[q]] + rk[q];
    }
#pragma unroll
    for (int q = 0; q < 4; q++) g_csrc[pos[q]] = src[q];
}

// ---------------- warp-per-dst softmax aggregation + fused BN partials ----------------
__global__ __launch_bounds__(256) void k_agg(const float* __restrict__ bias) {
    __shared__ float ss[8][132];
    __shared__ float sq[8][132];
    int g = blockIdx.x * blockDim.x + threadIdx.x;
    int w = g >> 5;
    int lane = g & 31;
    int wid = threadIdx.x >> 5;
    int h = lane >> 2;
    int c0 = lane * 4;

    float4 o = make_float4(0.f, 0.f, 0.f, 0.f);
    if (w < NN) {
        int start = g_rowptr[w], end = g_rowptr[w + 1];
        float adst = g_adst[w * 8 + h];
        float4 acc = make_float4(0.f, 0.f, 0.f, 0.f);
        float denom = 0.f;
        const uint2* xlp = (const uint2*)g_xlh;

        for (int base = start; base < end; base += 32) {
            int idx = base + lane;
            int mysrc = (idx < end) ? g_csrc[idx] : 0;
            int cnt = end - base; if (cnt > 32) cnt = 32;
            int j = 0;
            // explicit 4-edge pipeline: batch loads, then consume
            for (; j + 4 <= cnt; j += 4) {
                int s0 = __shfl_sync(0xffffffffu, mysrc, j);
                int s1 = __shfl_sync(0xffffffffu, mysrc, j + 1);
                int s2 = __shfl_sync(0xffffffffu, mysrc, j + 2);
                int s3 = __shfl_sync(0xffffffffu, mysrc, j + 3);
                float e0 = g_asrc[s0 * 8 + h];
                float e1 = g_asrc[s1 * 8 + h];
                float e2 = g_asrc[s2 * 8 + h];
                float e3 = g_asrc[s3 * 8 + h];
                uint2 u0 = xlp[(size_t)s0 * 32 + lane];
                uint2 u1 = xlp[(size_t)s1 * 32 + lane];
                uint2 u2 = xlp[(size_t)s2 * 32 + lane];
                uint2 u3 = xlp[(size_t)s3 * 32 + lane];
                e0 += adst; e1 += adst; e2 += adst; e3 += adst;
                e0 = fmaxf(e0, 0.2f * e0); e1 = fmaxf(e1, 0.2f * e1);
                e2 = fmaxf(e2, 0.2f * e2); e3 = fmaxf(e3, 0.2f * e3);
                float w0 = __expf(e0), w1 = __expf(e1);
                float w2 = __expf(e2), w3 = __expf(e3);
                denom += (w0 + w1) + (w2 + w3);
                float2 f;
                f = __half22float2(*(__half2*)&u0.x);
                acc.x = fmaf(w0, f.x, acc.x); acc.y = fmaf(w0, f.y, acc.y);
                f = __half22float2(*(__half2*)&u0.y);
                acc.z = fmaf(w0, f.x, acc.z); acc.w = fmaf(w0, f.y, acc.w);
                f = __half22float2(*(__half2*)&u1.x);
                acc.x = fmaf(w1, f.x, acc.x); acc.y = fmaf(w1, f.y, acc.y);
                f = __half22float2(*(__half2*)&u1.y);
                acc.z = fmaf(w1, f.x, acc.z); acc.w = fmaf(w1, f.y, acc.w);
                f = __half22float2(*(__half2*)&u2.x);
                acc.x = fmaf(w2, f.x, acc.x); acc.y = fmaf(w2, f.y, acc.y);
                f = __half22float2(*(__half2*)&u2.y);
                acc.z = fmaf(w2, f.x, acc.z); acc.w = fmaf(w2, f.y, acc.w);
                f = __half22float2(*(__half2*)&u3.x);
                acc.x = fmaf(w3, f.x, acc.x); acc.y = fmaf(w3, f.y, acc.y);
                f = __half22float2(*(__half2*)&u3.y);
                acc.z = fmaf(w3, f.x, acc.z); acc.w = fmaf(w3, f.y, acc.w);
            }
            for (; j < cnt; j++) {
                int src = __shfl_sync(0xffffffffu, mysrc, j);
                float e = g_asrc[src * 8 + h] + adst;
                e = fmaxf(e, 0.2f * e);
                float wq = __expf(e);
                uint2 u = xlp[(size_t)src * 32 + lane];
                float2 f0 = __half22float2(*(__half2*)&u.x);
                float2 f1 = __half22float2(*(__half2*)&u.y);
                denom += wq;
                acc.x = fmaf(wq, f0.x, acc.x);
                acc.y = fmaf(wq, f0.y, acc.y);
                acc.z = fmaf(wq, f1.x, acc.z);
                acc.w = fmaf(wq, f1.y, acc.w);
            }
        }
        float inv = 1.f / (denom + 1e-16f);
        float4 b = ((const float4*)bias)[lane];
        o.x = fmaf(acc.x, inv, b.x);
        o.y = fmaf(acc.y, inv, b.y);
        o.z = fmaf(acc.z, inv, b.z);
        o.w = fmaf(acc.w, inv, b.w);
        ((float4*)g_h)[(size_t)w * 32 + lane] = o;
    }

    // fused BN partial stats
    ss[wid][c0 + 0] = o.x; ss[wid][c0 + 1] = o.y;
    ss[wid][c0 + 2] = o.z; ss[wid][c0 + 3] = o.w;
    sq[wid][c0 + 0] = o.x * o.x; sq[wid][c0 + 1] = o.y * o.y;
    sq[wid][c0 + 2] = o.z * o.z; sq[wid][c0 + 3] = o.w * o.w;
    __syncthreads();
    int tid = threadIdx.x;
    if (tid < 128) {
        float s = 0.f, q = 0.f;
#pragma unroll
        for (int ww = 0; ww < 8; ww++) { s += ss[ww][tid]; q += sq[ww][tid]; }
        int slot = blockIdx.x & (NSLOT - 1);
        atomicAdd(&g_ps1[slot * 128 + tid], s);
        atomicAdd(&g_ps2[slot * 128 + tid], q);
    }
}

// ---------------- BN params ----------------
__global__ void k_bnp(const float* __restrict__ gamma,
                      const float* __restrict__ beta) {
    int c = threadIdx.x;
    double s = 0.0, q = 0.0;
    for (int b = 0; b < NSLOT; b++) {
        s += (double)g_ps1[b * 128 + c];
        q += (double)g_ps2[b * 128 + c];
    }
    double mean_d = s / (double)NN;
    double var_d = q / (double)NN - mean_d * mean_d;
    float sc = gamma[c] * rsqrtf((float)var_d + 1e-5f);
    g_scale[c] = sc;
    g_shift[c] = beta[c] - (float)mean_d * sc;
}

// ---------------- normalize + ReLU + residual + next-call housekeeping ----------------
__global__ void k_final(const float* __restrict__ x, float* __restrict__ out,
                        const unsigned int* __restrict__ ei) {
    int g = blockIdx.x * blockDim.x + threadIdx.x;   // NN*32 float4s
    // housekeeping for next replay (deterministic)
    if (g < NPART * NN) g_deg[g] = 0;
    if (g < NSLOT * 128) { g_ps1[g] = 0.f; g_ps2[g] = 0.f; }
    if (g == 0) g_is64 = detect64(ei);
    if (g >= NN * 32) return;
    int l = g & 31;
    float4 hv = ((const float4*)g_h)[g];
    float4 xv = ((const float4*)x)[g];
    float4 sc = ((const float4*)g_scale)[l];
    float4 sh = ((const float4*)g_shift)[l];
    float4 o;
    o.x = xv.x + fmaxf(0.f, fmaf(hv.x, sc.x, sh.x));
    o.y = xv.y + fmaxf(0.f, fmaf(hv.y, sc.y, sh.y));
    o.z = xv.z + fmaxf(0.f, fmaf(hv.z, sc.z, sh.z));
    o.w = xv.w + fmaxf(0.f, fmaf(hv.w, sc.w, sh.w));
    ((float4*)out)[g] = o;
}

// ---------------- launch ----------------
extern "C" void kernel_launch(void* const* d_in, const int* in_sizes, int n_in,
                              void* d_out, int out_size) {
    const float* x       = (const float*)d_in[0];
    const void*  ei      = d_in[1];
    const float* W       = (const float*)d_in[2];
    const float* att_src = (const float*)d_in[3];
    const float* att_dst = (const float*)d_in[4];
    const float* bias    = (const float*)d_in[5];
    const float* gamma   = (const float*)d_in[6];
    const float* beta    = (const float*)d_in[7];
    float* out = (float*)d_out;
    (void)in_sizes; (void)n_in; (void)out_size;

    const int EB = (NE + 255) / 256;          // 6250 hist blocks
    const int WB = (NN * 32 + 255) / 256;     // 6250

    k_fuse <<<GEMMB + EB, 256>>>(x, W, att_src, att_dst, ei);
    k_scan <<<1, 1024>>>();
    k_fill <<<(NE / 4 + 255) / 256, 256>>>(ei);
    k_agg  <<<WB, 256>>>(bias);
    k_bnp  <<<1, 128>>>(gamma, beta);
    k_final<<<WB, 256>>>(x, out, (const unsigned int*)ei);
}

// round 9
// speedup vs baseline: 1.5868x; 1.5868x over previous
#include <cuda_runtime.h>
#include <cuda_fp16.h>
#include <math.h>

#define NN 50000
#define NE 1600000
#define DD 128
#define HH 8
#define NPART 8
#define NSLOT 256
#define LOG2E 1.44269504088896f

// ---------------- scratch (no allocations allowed) ----------------
__device__ __half2 g_xlh[NN * 64];     // x @ W in fp16
__device__ float  g_h[NN * DD];        // pre-BN output
__device__ float  g_asrc[NN * HH];     // pre-scaled by log2(e)
__device__ float  g_adst[NN * HH];     // pre-scaled by log2(e)
__device__ int    g_deg[NPART * NN];   // zero at load; re-zeroed by k_final each call
__device__ int    g_cur[NPART * NN];
__device__ int    g_rank[NE];
__device__ int    g_rowptr[NN + 1];
__device__ int    g_csrc[NE];
__device__ float  g_ps1[NSLOT * 128];  // BN partials (zeroed by k_final)
__device__ float  g_ps2[NSLOT * 128];
__device__ float  g_scale[DD];
__device__ float  g_shift[DD];
__device__ int    g_is64 = -1;         // first call self-detects

// ---------------- f32x2 helpers ----------------
#define FMA2(d, a, b, c) \
    asm("fma.rn.f32x2 %0, %1, %2, %3;" : "=l"(d) : "l"(a), "l"(b), "l"(c))

__device__ __forceinline__ unsigned long long pk2(float v) {
    unsigned long long r;
    unsigned int u = __float_as_uint(v);
    asm("mov.b64 %0, {%1, %2};" : "=l"(r) : "r"(u), "r"(u));
    return r;
}
__device__ __forceinline__ void upk2(unsigned long long v, float& lo, float& hi) {
    unsigned int a, b;
    asm("mov.b64 {%0, %1}, %2;" : "=r"(a), "=r"(b) : "l"(v));
    lo = __uint_as_float(a);
    hi = __uint_as_float(b);
}

__device__ __forceinline__ int detect64(const unsigned int* w) {
    int is64 = 1;
    for (int j = 1; j < 64; j += 2)
        if (w[j] != 0u) { is64 = 0; break; }
    return is64;
}

__device__ __forceinline__ int edge_val(const void* ei, long long flat, int is64) {
    if (is64) return (int)((const long long*)ei)[flat];
    return ((const int*)ei)[flat];
}

// ---------------- hist: rank recording + 8-way partial histograms ----------------
__global__ void k_hist(const void* __restrict__ ei) {
    int e = blockIdx.x * blockDim.x + threadIdx.x;
    if (e >= NE) return;
    int is64 = g_is64;
    if (is64 < 0) is64 = detect64((const unsigned int*)ei);   // call-1 self-detect
    int dst = edge_val(ei, (long long)NE + e, is64);
    int part = e & (NPART - 1);
    g_rank[e] = atomicAdd(&g_deg[part * NN + dst], 1);
}

// ---------------- scan: rowptr + 8-way cursor bases ----------------
__global__ void k_scan() {
    __shared__ int warpsum[32];
    __shared__ int carry;
    int tid = threadIdx.x, lane = tid & 31, wid = tid >> 5;
    if (tid == 0) { carry = 0; g_rowptr[0] = 0; }
    __syncthreads();
    for (int base = 0; base < NN; base += 1024) {
        int i = base + tid;
        int d[NPART];
        int v = 0;
#pragma unroll
        for (int p = 0; p < NPART; p++) {
            d[p] = (i < NN) ? g_deg[p * NN + i] : 0;
            v += d[p];
        }
        int s = v;
#pragma unroll
        for (int off = 1; off < 32; off <<= 1) {
            int t = __shfl_up_sync(0xffffffffu, s, off);
            if (lane >= off) s += t;
        }
        if (lane == 31) warpsum[wid] = s;
        __syncthreads();
        if (wid == 0) {
            int ws = warpsum[lane];
            int ss = ws;
#pragma unroll
            for (int off = 1; off < 32; off <<= 1) {
                int t = __shfl_up_sync(0xffffffffu, ss, off);
                if (lane >= off) ss += t;
            }
            warpsum[lane] = ss - ws;
        }
        __syncthreads();
        int incl = s + warpsum[wid] + carry;
        if (i < NN) {
            g_rowptr[i + 1] = incl;
            int b = incl - v;
#pragma unroll
            for (int p = 0; p < NPART; p++) {
                g_cur[p * NN + i] = b;
                b += d[p];
            }
        }
        __syncthreads();
        if (tid == 1023) carry = incl;
        __syncthreads();
    }
}

// ---------------- fill: 4 edges/thread, no atomics ----------------
__global__ void k_fill(const void* __restrict__ ei) {
    int g = blockIdx.x * blockDim.x + threadIdx.x;   // NE/4 threads
    if (g >= NE / 4) return;
    int is64 = g_is64;
    if (is64 < 0) is64 = detect64((const unsigned int*)ei);
    int e0 = g * 4;
    int src[4], dst[4], rk[4];
    if (is64) {
#pragma unroll
        for (int q = 0; q < 4; q++) {
            src[q] = edge_val(ei, e0 + q, 1);
            dst[q] = edge_val(ei, (long long)NE + e0 + q, 1);
        }
    } else {
        int4 s4 = ((const int4*)ei)[g];
        int4 d4 = ((const int4*)ei)[NE / 4 + g];
        src[0] = s4.x; src[1] = s4.y; src[2] = s4.z; src[3] = s4.w;
        dst[0] = d4.x; dst[1] = d4.y; dst[2] = d4.z; dst[3] = d4.w;
    }
    int4 r4 = ((const int4*)g_rank)[g];
    rk[0] = r4.x; rk[1] = r4.y; rk[2] = r4.z; rk[3] = r4.w;
    int pos[4];
#pragma unroll
    for (int q = 0; q < 4; q++) {
        int part = (e0 + q) & (NPART - 1);
        pos[q] = g_cur[part * NN + dst[q]] + rk[q];
    }
#pragma unroll
    for (int q = 0; q < 4; q++) g_csrc[pos[q]] = src[q];
}

// ---------------- GEMM (f32x2) + fused logits (pre-scaled by log2e) + fp16 xl ----------------
__global__ __launch_bounds__(256, 2) void k_gemm(const float* __restrict__ x,
                                                 const float* __restrict__ W,
                                                 const float* __restrict__ att_src,
                                                 const float* __restrict__ att_dst) {
    __shared__ float xs[32][136];   // [k][row], padded
    __shared__ float ws[32][132];   // [k][col], padded
    int tid = threadIdx.x;
    int lane = tid & 31;
    int row0 = blockIdx.x * 128;
    int r0 = (tid >> 5) * 16;
    int c0 = lane * 4;

    unsigned long long acc[16][2];
#pragma unroll
    for (int i = 0; i < 16; i++) { acc[i][0] = 0ull; acc[i][1] = 0ull; }

#pragma unroll 1
    for (int kk = 0; kk < 128; kk += 32) {
        {   // W tile: 32 k-rows x 128 cols
            int lk = tid >> 3;
            int lc = (tid & 7) * 16;
            const float4* wp = (const float4*)(W + (size_t)(kk + lk) * 128 + lc);
            float4* q = (float4*)&ws[lk][lc];
            q[0] = wp[0]; q[1] = wp[1]; q[2] = wp[2]; q[3] = wp[3];
        }
        {   // x tile: 128 rows x 32 k, stored transposed
            int lr = tid >> 1;
            int k0 = (tid & 1) * 16;
            int grow = row0 + lr; if (grow >= NN) grow = NN - 1;
            const float* xp = x + (size_t)grow * 128 + kk + k0;
            float4 a = *(const float4*)xp;
            float4 b = *(const float4*)(xp + 4);
            float4 c = *(const float4*)(xp + 8);
            float4 d = *(const float4*)(xp + 12);
            xs[k0 + 0][lr] = a.x;  xs[k0 + 1][lr] = a.y;
            xs[k0 + 2][lr] = a.z;  xs[k0 + 3][lr] = a.w;
            xs[k0 + 4][lr] = b.x;  xs[k0 + 5][lr] = b.y;
            xs[k0 + 6][lr] = b.z;  xs[k0 + 7][lr] = b.w;
            xs[k0 + 8][lr] = c.x;  xs[k0 + 9][lr] = c.y;
            xs[k0 + 10][lr] = c.z; xs[k0 + 11][lr] = c.w;
            xs[k0 + 12][lr] = d.x; xs[k0 + 13][lr] = d.y;
            xs[k0 + 14][lr] = d.z; xs[k0 + 15][lr] = d.w;
        }
        __syncthreads();
#pragma unroll 4
        for (int k = 0; k < 32; k++) {
            ulonglong2 wv = *(const ulonglong2*)&ws[k][c0];
            float4 xa = *(const float4*)&xs[k][r0];
            float4 xb = *(const float4*)&xs[k][r0 + 4];
            float4 xc = *(const float4*)&xs[k][r0 + 8];
            float4 xd = *(const float4*)&xs[k][r0 + 12];
            float xr[16] = {xa.x, xa.y, xa.z, xa.w, xb.x, xb.y, xb.z, xb.w,
                            xc.x, xc.y, xc.z, xc.w, xd.x, xd.y, xd.z, xd.w};
#pragma unroll
            for (int i = 0; i < 16; i++) {
                unsigned long long xp2 = pk2(xr[i]);
                FMA2(acc[i][0], xp2, wv.x, acc[i][0]);
                FMA2(acc[i][1], xp2, wv.y, acc[i][1]);
            }
        }
        __syncthreads();
    }

    // epilogue: fp16 xl + attention logits scaled by log2(e)
    float4 asv = ((const float4*)att_src)[lane];
    float4 adv = ((const float4*)att_dst)[lane];
    int head = lane >> 2;
#pragma unroll
    for (int i = 0; i < 16; i++) {
        int r = row0 + r0 + i;
        float o0, o1, o2, o3;
        upk2(acc[i][0], o0, o1);
        upk2(acc[i][1], o2, o3);
        float ps = o0 * asv.x + o1 * asv.y + o2 * asv.z + o3 * asv.w;
        float pd = o0 * adv.x + o1 * adv.y + o2 * adv.z + o3 * adv.w;
        ps += __shfl_xor_sync(0xffffffffu, ps, 1);
        ps += __shfl_xor_sync(0xffffffffu, ps, 2);
        pd += __shfl_xor_sync(0xffffffffu, pd, 1);
        pd += __shfl_xor_sync(0xffffffffu, pd, 2);
        if (r < NN) {
            __half2 p0 = __float22half2_rn(make_float2(o0, o1));
            __half2 p1 = __float22half2_rn(make_float2(o2, o3));
            uint2 u;
            u.x = *(unsigned int*)&p0;
            u.y = *(unsigned int*)&p1;
            ((uint2*)g_xlh)[(size_t)r * 32 + lane] = u;
            if ((lane & 3) == 0) {
                g_asrc[r * 8 + head] = ps * LOG2E;
                g_adst[r * 8 + head] = pd * LOG2E;
            }
        }
    }
}

// ---------------- warp-per-dst aggregation: 2 edges/warp, 16 lanes/edge ----------------
// logits pre-scaled by log2e -> exp2f; no max-shift (|logit| small, exact same softmax value)
__global__ __launch_bounds__(256) void k_agg(const float* __restrict__ bias) {
    __shared__ float ss[8][136];
    __shared__ float sq[8][136];
    int g = blockIdx.x * blockDim.x + threadIdx.x;
    int w = g >> 5;
    int lane = g & 31;
    int wid = threadIdx.x >> 5;
    int half = lane >> 4;      // which edge of the pair
    int l = lane & 15;         // position within edge: 8 channels
    int h = l >> 1;            // head of channels 8l..8l+7

    float a0 = 0.f, a1 = 0.f, a2 = 0.f, a3 = 0.f;
    float a4 = 0.f, a5 = 0.f, a6 = 0.f, a7 = 0.f;
    float o0 = 0.f, o1 = 0.f, o2 = 0.f, o3 = 0.f;
    float o4 = 0.f, o5 = 0.f, o6 = 0.f, o7 = 0.f;

    if (w < NN) {
        int start = g_rowptr[w], end = g_rowptr[w + 1];
        float adst = g_adst[w * 8 + h];
        float denom = 0.f;
        const uint4* xlp = (const uint4*)g_xlh;   // row = 16 uint4

        for (int base = start; base < end; base += 32) {
            int idx = base + lane;
            int mysrc = (idx < end) ? g_csrc[idx] : 0;
            int cnt = end - base; if (cnt > 32) cnt = 32;
            for (int j = 0; j < cnt; j += 2) {
                int myj = j + half;                                   // lanes 0-15: j, 16-31: j+1
                int src = __shfl_sync(0xffffffffu, mysrc, myj);       // per-lane source index
                bool act = myj < cnt;
                float e = g_asrc[src * 8 + h] + adst;
                e = fmaxf(e, 0.2f * e);                               // leaky relu (pre-scaled)
                float wq = act ? exp2f(e) : 0.f;
                uint4 u = xlp[(size_t)src * 16 + l];
                float2 f;
                f = __half22float2(*(__half2*)&u.x);
                a0 = fmaf(wq, f.x, a0); a1 = fmaf(wq, f.y, a1);
                f = __half22float2(*(__half2*)&u.y);
                a2 = fmaf(wq, f.x, a2); a3 = fmaf(wq, f.y, a3);
                f = __half22float2(*(__half2*)&u.z);
                a4 = fmaf(wq, f.x, a4); a5 = fmaf(wq, f.y, a5);
                f = __half22float2(*(__half2*)&u.w);
                a6 = fmaf(wq, f.x, a6); a7 = fmaf(wq, f.y, a7);
                denom += wq;
            }
        }
        // merge the two edge-parity halves (lane l pairs with lane l+16)
        denom += __shfl_xor_sync(0xffffffffu, denom, 16);
        a0 += __shfl_xor_sync(0xffffffffu, a0, 16);
        a1 += __shfl_xor_sync(0xffffffffu, a1, 16);
        a2 += __shfl_xor_sync(0xffffffffu, a2, 16);
        a3 += __shfl_xor_sync(0xffffffffu, a3, 16);
        a4 += __shfl_xor_sync(0xffffffffu, a4, 16);
        a5 += __shfl_xor_sync(0xffffffffu, a5, 16);
        a6 += __shfl_xor_sync(0xffffffffu, a6, 16);
        a7 += __shfl_xor_sync(0xffffffffu, a7, 16);
        float inv = 1.f / (denom + 1e-16f);
        float4 b0 = ((const float4*)bias)[l * 2];
        float4 b1 = ((const float4*)bias)[l * 2 + 1];
        o0 = fmaf(a0, inv, b0.x); o1 = fmaf(a1, inv, b0.y);
        o2 = fmaf(a2, inv, b0.z); o3 = fmaf(a3, inv, b0.w);
        o4 = fmaf(a4, inv, b1.x); o5 = fmaf(a5, inv, b1.y);
        o6 = fmaf(a6, inv, b1.z); o7 = fmaf(a7, inv, b1.w);
        if (half == 0) {
            float4 v0 = {o0, o1, o2, o3};
            float4 v1 = {o4, o5, o6, o7};
            ((float4*)g_h)[(size_t)w * 32 + l * 2] = v0;
            ((float4*)g_h)[(size_t)w * 32 + l * 2 + 1] = v1;
        }
    }

    // fused BN partial stats: half-0 lanes cover all 128 channels of this warp's node
    if (half == 0) {
        float4 v0 = {o0, o1, o2, o3};
        float4 v1 = {o4, o5, o6, o7};
        float4 q0 = {o0 * o0, o1 * o1, o2 * o2, o3 * o3};
        float4 q1 = {o4 * o4, o5 * o5, o6 * o6, o7 * o7};
        *(float4*)&ss[wid][l * 8] = v0;
        *(float4*)&ss[wid][l * 8 + 4] = v1;
        *(float4*)&sq[wid][l * 8] = q0;
        *(float4*)&sq[wid][l * 8 + 4] = q1;
    }
    __syncthreads();
    int tid = threadIdx.x;
    if (tid < 128) {
        float s = 0.f, q = 0.f;
#pragma unroll
        for (int ww = 0; ww < 8; ww++) { s += ss[ww][tid]; q += sq[ww][tid]; }
        int slot = blockIdx.x & (NSLOT - 1);
        atomicAdd(&g_ps1[slot * 128 + tid], s);
        atomicAdd(&g_ps2[slot * 128 + tid], q);
    }
}

// ---------------- BN params ----------------
__global__ void k_bnp(const float* __restrict__ gamma,
                      const float* __restrict__ beta) {
    int c = threadIdx.x;
    double s = 0.0, q = 0.0;
    for (int b = 0; b < NSLOT; b++) {
        s += (double)g_ps1[b * 128 + c];
        q += (double)g_ps2[b * 128 + c];
    }
    double mean_d = s / (double)NN;
    double var_d = q / (double)NN - mean_d * mean_d;
    float sc = gamma[c] * rsqrtf((float)var_d + 1e-5f);
    g_scale[c] = sc;
    g_shift[c] = beta[c] - (float)mean_d * sc;
}

// ---------------- normalize + ReLU + residual + next-call housekeeping ----------------
__global__ void k_final(const float* __restrict__ x, float* __restrict__ out,
                        const unsigned int* __restrict__ ei) {
    int g = blockIdx.x * blockDim.x + threadIdx.x;   // NN*32 float4s
    if (g < NPART * NN) g_deg[g] = 0;
    if (g < NSLOT * 128) { g_ps1[g] = 0.f; g_ps2[g] = 0.f; }
    if (g == 0) g_is64 = detect64(ei);
    if (g >= NN * 32) return;
    int l = g & 31;
    float4 hv = ((const float4*)g_h)[g];
    float4 xv = ((const float4*)x)[g];
    float4 sc = ((const float4*)g_scale)[l];
    float4 sh = ((const float4*)g_shift)[l];
    float4 o;
    o.x = xv.x + fmaxf(0.f, fmaf(hv.x, sc.x, sh.x));
    o.y = xv.y + fmaxf(0.f, fmaf(hv.y, sc.y, sh.y));
    o.z = xv.z + fmaxf(0.f, fmaf(hv.z, sc.z, sh.z));
    o.w = xv.w + fmaxf(0.f, fmaf(hv.w, sc.w, sh.w));
    ((float4*)out)[g] = o;
}

// ---------------- launch ----------------
extern "C" void kernel_launch(void* const* d_in, const int* in_sizes, int n_in,
                              void* d_out, int out_size) {
    const float* x       = (const float*)d_in[0];
    const void*  ei      = d_in[1];
    const float* W       = (const float*)d_in[2];
    const float* att_src = (const float*)d_in[3];
    const float* att_dst = (const float*)d_in[4];
    const float* bias    = (const float*)d_in[5];
    const float* gamma   = (const float*)d_in[6];
    const float* beta    = (const float*)d_in[7];
    float* out = (float*)d_out;
    (void)in_sizes; (void)n_in; (void)out_size;

    const int EB = (NE + 255) / 256;          // 6250
    const int WB = (NN * 32 + 255) / 256;     // 6250

    k_hist <<<EB, 256>>>(ei);
    k_scan <<<1, 1024>>>();
    k_fill <<<(NE / 4 + 255) / 256, 256>>>(ei);
    k_gemm <<<(NN + 127) / 128, 256>>>(x, W, att_src, att_dst);  // right before agg: xlh hot in L2
    k_agg  <<<WB, 256>>>(bias);
    k_bnp  <<<1, 128>>>(gamma, beta);
    k_final<<<WB, 256>>>(x, out, (const unsigned int*)ei);
}

// round 10
// speedup vs baseline: 1.8490x; 1.1652x over previous
#include <cuda_runtime.h>
#include <cuda_fp16.h>
#include <math.h>

#define NN 50000
#define NE 1600000
#define DD 128
#define HH 8
#define NPART 8
#define NSLOT 64
#define LOG2E 1.44269504088896f

// ---------------- scratch (no allocations allowed) ----------------
__device__ __half2 g_xlh[NN * 64];     // x @ W in fp16
__device__ float  g_h[NN * DD];        // pre-BN output
__device__ float  g_asrc[NN * HH];     // pre-scaled by log2(e)
__device__ float  g_adst[NN * HH];     // pre-scaled by log2(e)
__device__ int    g_deg[NPART * NN];   // zero at load; re-zeroed by k_final each call
__device__ int    g_cur[NPART * NN];
__device__ int    g_rank[NE];
__device__ int    g_rowptr[NN + 1];
__device__ int    g_csrc[NE];
__device__ float  g_ps1[NSLOT * 128];  // BN partials (zeroed by k_final)
__device__ float  g_ps2[NSLOT * 128];
__device__ float  g_scale[DD];
__device__ float  g_shift[DD];
__device__ int    g_is64 = -1;         // first call self-detects

// ---------------- helpers ----------------
#define FMA2(d, a, b, c) \
    asm("fma.rn.f32x2 %0, %1, %2, %3;" : "=l"(d) : "l"(a), "l"(b), "l"(c))

__device__ __forceinline__ unsigned long long pk2(float v) {
    unsigned long long r;
    unsigned int u = __float_as_uint(v);
    asm("mov.b64 %0, {%1, %2};" : "=l"(r) : "r"(u), "r"(u));
    return r;
}
__device__ __forceinline__ void upk2(unsigned long long v, float& lo, float& hi) {
    unsigned int a, b;
    asm("mov.b64 {%0, %1}, %2;" : "=r"(a), "=r"(b) : "l"(v));
    lo = __uint_as_float(a);
    hi = __uint_as_float(b);
}
__device__ __forceinline__ float ex2f(float x) {          // guaranteed single MUFU
    float y;
    asm("ex2.approx.ftz.f32 %0, %1;" : "=f"(y) : "f"(x));
    return y;
}

__device__ __forceinline__ int detect64(const unsigned int* w) {
    int is64 = 1;
    for (int j = 1; j < 64; j += 2)
        if (w[j] != 0u) { is64 = 0; break; }
    return is64;
}

__device__ __forceinline__ int edge_val(const void* ei, long long flat, int is64) {
    if (is64) return (int)((const long long*)ei)[flat];
    return ((const int*)ei)[flat];
}

// ---------------- hist: rank recording + 8-way partial histograms ----------------
__global__ void k_hist(const void* __restrict__ ei) {
    int e = blockIdx.x * blockDim.x + threadIdx.x;
    if (e >= NE) return;
    int is64 = g_is64;
    if (is64 < 0) is64 = detect64((const unsigned int*)ei);   // call-1 self-detect
    int dst = edge_val(ei, (long long)NE + e, is64);
    int part = e & (NPART - 1);
    g_rank[e] = atomicAdd(&g_deg[part * NN + dst], 1);
}

// ---------------- scan: 4 nodes/thread, int4 vectorized ----------------
__global__ void k_scan() {
    __shared__ int warpsum[32];
    __shared__ int carry;
    int tid = threadIdx.x, lane = tid & 31, wid = tid >> 5;
    if (tid == 0) { carry = 0; g_rowptr[0] = 0; }
    __syncthreads();
    for (int base = 0; base < NN; base += 4096) {
        int i0 = base + tid * 4;
        bool ok = i0 < NN;                    // NN % 4 == 0, so all 4 valid when ok
        int4 d[NPART];
        int v0 = 0, v1 = 0, v2 = 0, v3 = 0;
#pragma unroll
        for (int p = 0; p < NPART; p++) {
            d[p] = ok ? *(const int4*)&g_deg[p * NN + i0] : make_int4(0, 0, 0, 0);
            v0 += d[p].x; v1 += d[p].y; v2 += d[p].z; v3 += d[p].w;
        }
        int v = v0 + v1 + v2 + v3;
        int s = v;
#pragma unroll
        for (int off = 1; off < 32; off <<= 1) {
            int t = __shfl_up_sync(0xffffffffu, s, off);
            if (lane >= off) s += t;
        }
        if (lane == 31) warpsum[wid] = s;
        __syncthreads();
        if (wid == 0) {
            int ws = warpsum[lane];
            int ss = ws;
#pragma unroll
            for (int off = 1; off < 32; off <<= 1) {
                int t = __shfl_up_sync(0xffffffffu, ss, off);
                if (lane >= off) ss += t;
            }
            warpsum[lane] = ss - ws;
        }
        __syncthreads();
        int incl = s + warpsum[wid] + carry;
        if (ok) {
            int b0 = incl - v;
            int b1 = b0 + v0, b2 = b1 + v1, b3 = b2 + v2;
            g_rowptr[i0 + 1] = b1; g_rowptr[i0 + 2] = b2;
            g_rowptr[i0 + 3] = b3; g_rowptr[i0 + 4] = b3 + v3;
            int c0 = b0, c1 = b1, c2 = b2, c3 = b3;
#pragma unroll
            for (int p = 0; p < NPART; p++) {
                *(int4*)&g_cur[p * NN + i0] = make_int4(c0, c1, c2, c3);
                c0 += d[p].x; c1 += d[p].y; c2 += d[p].z; c3 += d[p].w;
            }
        }
        __syncthreads();
        if (tid == 1023) carry = incl;
        __syncthreads();
    }
}

// ---------------- fill: 4 edges/thread, no atomics ----------------
__global__ void k_fill(const void* __restrict__ ei) {
    int g = blockIdx.x * blockDim.x + threadIdx.x;   // NE/4 threads
    if (g >= NE / 4) return;
    int is64 = g_is64;
    if (is64 < 0) is64 = detect64((const unsigned int*)ei);
    int e0 = g * 4;
    int src[4], dst[4], rk[4];
    if (is64) {
#pragma unroll
        for (int q = 0; q < 4; q++) {
            src[q] = edge_val(ei, e0 + q, 1);
            dst[q] = edge_val(ei, (long long)NE + e0 + q, 1);
        }
    } else {
        int4 s4 = ((const int4*)ei)[g];
        int4 d4 = ((const int4*)ei)[NE / 4 + g];
        src[0] = s4.x; src[1] = s4.y; src[2] = s4.z; src[3] = s4.w;
        dst[0] = d4.x; dst[1] = d4.y; dst[2] = d4.z; dst[3] = d4.w;
    }
    int4 r4 = ((const int4*)g_rank)[g];
    rk[0] = r4.x; rk[1] = r4.y; rk[2] = r4.z; rk[3] = r4.w;
    int pos[4];
#pragma unroll
    for (int q = 0; q < 4; q++) {
        int part = (e0 + q) & (NPART - 1);
        pos[q] = g_cur[part * NN + dst[q]] + rk[q];
    }
#pragma unroll
    for (int q = 0; q < 4; q++) g_csrc[pos[q]] = src[q];
}

// ---------------- GEMM (f32x2) + fused logits (pre-scaled by log2e) + fp16 xl ----------------
__global__ __launch_bounds__(256, 2) void k_gemm(const float* __restrict__ x,
                                                 const float* __restrict__ W,
                                                 const float* __restrict__ att_src,
                                                 const float* __restrict__ att_dst) {
    __shared__ float xs[32][136];   // [k][row], padded
    __shared__ float ws[32][132];   // [k][col], padded
    int tid = threadIdx.x;
    int lane = tid & 31;
    int row0 = blockIdx.x * 128;
    int r0 = (tid >> 5) * 16;
    int c0 = lane * 4;

    unsigned long long acc[16][2];
#pragma unroll
    for (int i = 0; i < 16; i++) { acc[i][0] = 0ull; acc[i][1] = 0ull; }

#pragma unroll 1
    for (int kk = 0; kk < 128; kk += 32) {
        {   // W tile: 32 k-rows x 128 cols
            int lk = tid >> 3;
            int lc = (tid & 7) * 16;
            const float4* wp = (const float4*)(W + (size_t)(kk + lk) * 128 + lc);
            float4* q = (float4*)&ws[lk][lc];
            q[0] = wp[0]; q[1] = wp[1]; q[2] = wp[2]; q[3] = wp[3];
        }
        {   // x tile: 128 rows x 32 k, stored transposed
            int lr = tid >> 1;
            int k0 = (tid & 1) * 16;
            int grow = row0 + lr; if (grow >= NN) grow = NN - 1;
            const float* xp = x + (size_t)grow * 128 + kk + k0;
            float4 a = *(const float4*)xp;
            float4 b = *(const float4*)(xp + 4);
            float4 c = *(const float4*)(xp + 8);
            float4 d = *(const float4*)(xp + 12);
            xs[k0 + 0][lr] = a.x;  xs[k0 + 1][lr] = a.y;
            xs[k0 + 2][lr] = a.z;  xs[k0 + 3][lr] = a.w;
            xs[k0 + 4][lr] = b.x;  xs[k0 + 5][lr] = b.y;
            xs[k0 + 6][lr] = b.z;  xs[k0 + 7][lr] = b.w;
            xs[k0 + 8][lr] = c.x;  xs[k0 + 9][lr] = c.y;
            xs[k0 + 10][lr] = c.z; xs[k0 + 11][lr] = c.w;
            xs[k0 + 12][lr] = d.x; xs[k0 + 13][lr] = d.y;
            xs[k0 + 14][lr] = d.z; xs[k0 + 15][lr] = d.w;
        }
        __syncthreads();
#pragma unroll 4
        for (int k = 0; k < 32; k++) {
            ulonglong2 wv = *(const ulonglong2*)&ws[k][c0];
            float4 xa = *(const float4*)&xs[k][r0];
            float4 xb = *(const float4*)&xs[k][r0 + 4];
            float4 xc = *(const float4*)&xs[k][r0 + 8];
            float4 xd = *(const float4*)&xs[k][r0 + 12];
            float xr[16] = {xa.x, xa.y, xa.z, xa.w, xb.x, xb.y, xb.z, xb.w,
                            xc.x, xc.y, xc.z, xc.w, xd.x, xd.y, xd.z, xd.w};
#pragma unroll
            for (int i = 0; i < 16; i++) {
                unsigned long long xp2 = pk2(xr[i]);
                FMA2(acc[i][0], xp2, wv.x, acc[i][0]);
                FMA2(acc[i][1], xp2, wv.y, acc[i][1]);
            }
        }
        __syncthreads();
    }

    // epilogue: fp16 xl + attention logits scaled by log2(e)
    float4 asv = ((const float4*)att_src)[lane];
    float4 adv = ((const float4*)att_dst)[lane];
    int head = lane >> 2;
#pragma unroll
    for (int i = 0; i < 16; i++) {
        int r = row0 + r0 + i;
        float o0, o1, o2, o3;
        upk2(acc[i][0], o0, o1);
        upk2(acc[i][1], o2, o3);
        float ps = o0 * asv.x + o1 * asv.y + o2 * asv.z + o3 * asv.w;
        float pd = o0 * adv.x + o1 * adv.y + o2 * adv.z + o3 * adv.w;
        ps += __shfl_xor_sync(0xffffffffu, ps, 1);
        ps += __shfl_xor_sync(0xffffffffu, ps, 2);
        pd += __shfl_xor_sync(0xffffffffu, pd, 1);
        pd += __shfl_xor_sync(0xffffffffu, pd, 2);
        if (r < NN) {
            __half2 p0 = __float22half2_rn(make_float2(o0, o1));
            __half2 p1 = __float22half2_rn(make_float2(o2, o3));
            uint2 u;
            u.x = *(unsigned int*)&p0;
            u.y = *(unsigned int*)&p1;
            ((uint2*)g_xlh)[(size_t)r * 32 + lane] = u;
            if ((lane & 3) == 0) {
                g_asrc[r * 8 + head] = ps * LOG2E;
                g_adst[r * 8 + head] = pd * LOG2E;
            }
        }
    }
}

// ---------------- warp-per-dst aggregation: 2 edges/warp, 16 lanes/edge ----------------
// logits pre-scaled by log2e -> ex2.approx; no max-shift (|logit| small, same softmax value)
__global__ __launch_bounds__(256) void k_agg(const float* __restrict__ bias) {
    __shared__ float ss[8][136];
    __shared__ float sq[8][136];
    int g = blockIdx.x * blockDim.x + threadIdx.x;
    int w = g >> 5;
    int lane = g & 31;
    int wid = threadIdx.x >> 5;
    int half = lane >> 4;      // which edge of the pair
    int l = lane & 15;         // position within edge: 8 channels
    int h = l >> 1;            // head of channels 8l..8l+7

    float a0 = 0.f, a1 = 0.f, a2 = 0.f, a3 = 0.f;
    float a4 = 0.f, a5 = 0.f, a6 = 0.f, a7 = 0.f;
    float o0 = 0.f, o1 = 0.f, o2 = 0.f, o3 = 0.f;
    float o4 = 0.f, o5 = 0.f, o6 = 0.f, o7 = 0.f;

    if (w < NN) {
        int start = g_rowptr[w], end = g_rowptr[w + 1];
        float adst = g_adst[w * 8 + h];
        float denom = 0.f;
        const uint4* xlp = (const uint4*)g_xlh;   // row = 16 uint4

        for (int base = start; base < end; base += 32) {
            int idx = base + lane;
            int mysrc = (idx < end) ? g_csrc[idx] : 0;
            int cnt = end - base; if (cnt > 32) cnt = 32;
#pragma unroll 2
            for (int j = 0; j < cnt; j += 2) {
                int myj = j + half;                                   // lanes 0-15: j, 16-31: j+1
                int src = __shfl_sync(0xffffffffu, mysrc, myj);       // per-lane source index
                float e = g_asrc[src * 8 + h] + adst;
                e = fmaxf(e, 0.2f * e);                               // leaky relu (pre-scaled)
                float wq = ex2f(e);
                wq = (myj < cnt) ? wq : 0.f;
                uint4 u = xlp[(size_t)src * 16 + l];
                float2 f;
                f = __half22float2(*(__half2*)&u.x);
                a0 = fmaf(wq, f.x, a0); a1 = fmaf(wq, f.y, a1);
                f = __half22float2(*(__half2*)&u.y);
                a2 = fmaf(wq, f.x, a2); a3 = fmaf(wq, f.y, a3);
                f = __half22float2(*(__half2*)&u.z);
                a4 = fmaf(wq, f.x, a4); a5 = fmaf(wq, f.y, a5);
                f = __half22float2(*(__half2*)&u.w);
                a6 = fmaf(wq, f.x, a6); a7 = fmaf(wq, f.y, a7);
                denom += wq;
            }
        }
        // merge the two edge-parity halves (lane l pairs with lane l+16)
        denom += __shfl_xor_sync(0xffffffffu, denom, 16);
        a0 += __shfl_xor_sync(0xffffffffu, a0, 16);
        a1 += __shfl_xor_sync(0xffffffffu, a1, 16);
        a2 += __shfl_xor_sync(0xffffffffu, a2, 16);
        a3 += __shfl_xor_sync(0xffffffffu, a3, 16);
        a4 += __shfl_xor_sync(0xffffffffu, a4, 16);
        a5 += __shfl_xor_sync(0xffffffffu, a5, 16);
        a6 += __shfl_xor_sync(0xffffffffu, a6, 16);
        a7 += __shfl_xor_sync(0xffffffffu, a7, 16);
        float inv = 1.f / (denom + 1e-16f);
        float4 b0 = ((const float4*)bias)[l * 2];
        float4 b1 = ((const float4*)bias)[l * 2 + 1];
        o0 = fmaf(a0, inv, b0.x); o1 = fmaf(a1, inv, b0.y);
        o2 = fmaf(a2, inv, b0.z); o3 = fmaf(a3, inv, b0.w);
        o4 = fmaf(a4, inv, b1.x); o5 = fmaf(a5, inv, b1.y);
        o6 = fmaf(a6, inv, b1.z); o7 = fmaf(a7, inv, b1.w);
        if (half == 0) {
            float4 v0 = {o0, o1, o2, o3};
            float4 v1 = {o4, o5, o6, o7};
            ((float4*)g_h)[(size_t)w * 32 + l * 2] = v0;
            ((float4*)g_h)[(size_t)w * 32 + l * 2 + 1] = v1;
        }
    }

    // fused BN partial stats: half-0 lanes cover all 128 channels of this warp's node
    if (half == 0) {
        float4 v0 = {o0, o1, o2, o3};
        float4 v1 = {o4, o5, o6, o7};
        float4 q0 = {o0 * o0, o1 * o1, o2 * o2, o3 * o3};
        float4 q1 = {o4 * o4, o5 * o5, o6 * o6, o7 * o7};
        *(float4*)&ss[wid][l * 8] = v0;
        *(float4*)&ss[wid][l * 8 + 4] = v1;
        *(float4*)&sq[wid][l * 8] = q0;
        *(float4*)&sq[wid][l * 8 + 4] = q1;
    }
    __syncthreads();
    int tid = threadIdx.x;
    if (tid < 128) {
        float s = 0.f, q = 0.f;
#pragma unroll
        for (int ww = 0; ww < 8; ww++) { s += ss[ww][tid]; q += sq[ww][tid]; }
        int slot = blockIdx.x & (NSLOT - 1);
        atomicAdd(&g_ps1[slot * 128 + tid], s);
        atomicAdd(&g_ps2[slot * 128 + tid], q);
    }
}

// ---------------- BN params ----------------
__global__ void k_bnp(const float* __restrict__ gamma,
                      const float* __restrict__ beta) {
    int c = threadIdx.x;
    double s = 0.0, q = 0.0;
    for (int b = 0; b < NSLOT; b++) {
        s += (double)g_ps1[b * 128 + c];
        q += (double)g_ps2[b * 128 + c];
    }
    double mean_d = s / (double)NN;
    double var_d = q / (double)NN - mean_d * mean_d;
    float sc = gamma[c] * rsqrtf((float)var_d + 1e-5f);
    g_scale[c] = sc;
    g_shift[c] = beta[c] - (float)mean_d * sc;
}

// ---------------- normalize + ReLU + residual + next-call housekeeping ----------------
__global__ void k_final(const float* __restrict__ x, float* __restrict__ out,
                        const unsigned int* __restrict__ ei) {
    int g = blockIdx.x * blockDim.x + threadIdx.x;   // NN*32 float4s
    if (g < NPART * NN) g_deg[g] = 0;
    if (g < NSLOT * 128) { g_ps1[g] = 0.f; g_ps2[g] = 0.f; }
    if (g == 0) g_is64 = detect64(ei);
    if (g >= NN * 32) return;
    int l = g & 31;
    float4 hv = ((const float4*)g_h)[g];
    float4 xv = ((const float4*)x)[g];
    float4 sc = ((const float4*)g_scale)[l];
    float4 sh = ((const float4*)g_shift)[l];
    float4 o;
    o.x = xv.x + fmaxf(0.f, fmaf(hv.x, sc.x, sh.x));
    o.y = xv.y + fmaxf(0.f, fmaf(hv.y, sc.y, sh.y));
    o.z = xv.z + fmaxf(0.f, fmaf(hv.z, sc.z, sh.z));
    o.w = xv.w + fmaxf(0.f, fmaf(hv.w, sc.w, sh.w));
    ((float4*)out)[g] = o;
}

// ---------------- launch ----------------
extern "C" void kernel_launch(void* const* d_in, const int* in_sizes, int n_in,
                              void* d_out, int out_size) {
    const float* x       = (const float*)d_in[0];
    const void*  ei      = d_in[1];
    const float* W       = (const float*)d_in[2];
    const float* att_src = (const float*)d_in[3];
    const float* att_dst = (const float*)d_in[4];
    const float* bias    = (const float*)d_in[5];
    const float* gamma   = (const float*)d_in[6];
    const float* beta    = (const float*)d_in[7];
    float* out = (float*)d_out;
    (void)in_sizes; (void)n_in; (void)out_size;

    const int EB = (NE + 255) / 256;          // 6250
    const int WB = (NN * 32 + 255) / 256;     // 6250

    k_hist <<<EB, 256>>>(ei);
    k_scan <<<1, 1024>>>();
    k_fill <<<(NE / 4 + 255) / 256, 256>>>(ei);
    k_gemm <<<(NN + 127) / 128, 256>>>(x, W, att_src, att_dst);  // right before agg: xlh hot in L2
    k_agg  <<<WB, 256>>>(bias);
    k_bnp  <<<1, 128>>>(gamma, beta);
    k_final<<<WB, 256>>>(x, out, (const unsigned int*)ei);
}

// round 11
// speedup vs baseline: 2.0194x; 1.0921x over previous
#include <cuda_runtime.h>
#include <cuda_fp16.h>
#include <math.h>

#define NN 50000
#define NE 1600000
#define DD 128
#define HH 8
#define NPART 8
#define NSLOT 64
#define LOG2E 1.44269504088896f

// ---------------- scratch (no allocations allowed) ----------------
__device__ __half2 g_xlh[NN * 64];     // x @ W in fp16
__device__ float  g_h[NN * DD];        // pre-BN output
__device__ float  g_asrc[NN * HH];     // pre-scaled by log2(e)
__device__ float  g_adst[NN * HH];     // pre-scaled by log2(e)
__device__ int    g_deg[NPART * NN];   // zero at load; re-zeroed by k_final each call
__device__ int    g_cur[NPART * NN];
__device__ int    g_rank[NE];
__device__ int    g_rowptr[NN + 1];
__device__ int    g_csrc[NE];
__device__ float  g_ps1[NSLOT * 128];  // BN partials (zeroed by k_final)
__device__ float  g_ps2[NSLOT * 128];
__device__ float  g_scale[DD];
__device__ float  g_shift[DD];
__device__ int    g_is64 = -1;         // first call self-detects

// ---------------- helpers ----------------
#define FMA2(d, a, b, c) \
    asm("fma.rn.f32x2 %0, %1, %2, %3;" : "=l"(d) : "l"(a), "l"(b), "l"(c))

__device__ __forceinline__ unsigned long long pk2(float v) {
    unsigned long long r;
    unsigned int u = __float_as_uint(v);
    asm("mov.b64 %0, {%1, %2};" : "=l"(r) : "r"(u), "r"(u));
    return r;
}
__device__ __forceinline__ void upk2(unsigned long long v, float& lo, float& hi) {
    unsigned int a, b;
    asm("mov.b64 {%0, %1}, %2;" : "=r"(a), "=r"(b) : "l"(v));
    lo = __uint_as_float(a);
    hi = __uint_as_float(b);
}
__device__ __forceinline__ float ex2f(float x) {          // guaranteed single MUFU
    float y;
    asm("ex2.approx.ftz.f32 %0, %1;" : "=f"(y) : "f"(x));
    return y;
}

__device__ __forceinline__ int detect64(const unsigned int* w) {
    int is64 = 1;
    for (int j = 1; j < 64; j += 2)
        if (w[j] != 0u) { is64 = 0; break; }
    return is64;
}

__device__ __forceinline__ int edge_val(const void* ei, long long flat, int is64) {
    if (is64) return (int)((const long long*)ei)[flat];
    return ((const int*)ei)[flat];
}

// ---------------- hist: 2 edges/thread, rank recording + 8-way partials ----------------
__global__ void k_hist(const void* __restrict__ ei) {
    int g = blockIdx.x * blockDim.x + threadIdx.x;   // NE/2 threads
    if (g >= NE / 2) return;
    int is64 = g_is64;
    if (is64 < 0) is64 = detect64((const unsigned int*)ei);   // call-1 self-detect
    int e0 = g * 2;
    int d0, d1;
    if (is64) {
        d0 = edge_val(ei, (long long)NE + e0, 1);
        d1 = edge_val(ei, (long long)NE + e0 + 1, 1);
    } else {
        int2 dd = ((const int2*)ei)[NE / 2 + g];
        d0 = dd.x; d1 = dd.y;
    }
    int p0 = e0 & (NPART - 1);
    int p1 = (e0 + 1) & (NPART - 1);
    int r0 = atomicAdd(&g_deg[p0 * NN + d0], 1);
    int r1 = atomicAdd(&g_deg[p1 * NN + d1], 1);
    *(int2*)&g_rank[e0] = make_int2(r0, r1);
}

// ---------------- scan: 4 nodes/thread, int4 vectorized ----------------
__global__ void k_scan() {
    __shared__ int warpsum[32];
    __shared__ int carry;
    int tid = threadIdx.x, lane = tid & 31, wid = tid >> 5;
    if (tid == 0) { carry = 0; g_rowptr[0] = 0; }
    __syncthreads();
    for (int base = 0; base < NN; base += 4096) {
        int i0 = base + tid * 4;
        bool ok = i0 < NN;                    // NN % 4 == 0
        int4 d[NPART];
        int v0 = 0, v1 = 0, v2 = 0, v3 = 0;
#pragma unroll
        for (int p = 0; p < NPART; p++) {
            d[p] = ok ? *(const int4*)&g_deg[p * NN + i0] : make_int4(0, 0, 0, 0);
            v0 += d[p].x; v1 += d[p].y; v2 += d[p].z; v3 += d[p].w;
        }
        int v = v0 + v1 + v2 + v3;
        int s = v;
#pragma unroll
        for (int off = 1; off < 32; off <<= 1) {
            int t = __shfl_up_sync(0xffffffffu, s, off);
            if (lane >= off) s += t;
        }
        if (lane == 31) warpsum[wid] = s;
        __syncthreads();
        if (wid == 0) {
            int ws = warpsum[lane];
            int ss = ws;
#pragma unroll
            for (int off = 1; off < 32; off <<= 1) {
                int t = __shfl_up_sync(0xffffffffu, ss, off);
                if (lane >= off) ss += t;
            }
            warpsum[lane] = ss - ws;
        }
        __syncthreads();
        int incl = s + warpsum[wid] + carry;
        if (ok) {
            int b0 = incl - v;
            int b1 = b0 + v0, b2 = b1 + v1, b3 = b2 + v2;
            g_rowptr[i0 + 1] = b1; g_rowptr[i0 + 2] = b2;
            g_rowptr[i0 + 3] = b3; g_rowptr[i0 + 4] = b3 + v3;
            int c0 = b0, c1 = b1, c2 = b2, c3 = b3;
#pragma unroll
            for (int p = 0; p < NPART; p++) {
                *(int4*)&g_cur[p * NN + i0] = make_int4(c0, c1, c2, c3);
                c0 += d[p].x; c1 += d[p].y; c2 += d[p].z; c3 += d[p].w;
            }
        }
        __syncthreads();
        if (tid == 1023) carry = incl;
        __syncthreads();
    }
}

// ---------------- fill: 4 edges/thread, no atomics ----------------
__global__ void k_fill(const void* __restrict__ ei) {
    int g = blockIdx.x * blockDim.x + threadIdx.x;   // NE/4 threads
    if (g >= NE / 4) return;
    int is64 = g_is64;
    if (is64 < 0) is64 = detect64((const unsigned int*)ei);
    int e0 = g * 4;
    int src[4], dst[4], rk[4];
    if (is64) {
#pragma unroll
        for (int q = 0; q < 4; q++) {
            src[q] = edge_val(ei, e0 + q, 1);
            dst[q] = edge_val(ei, (long long)NE + e0 + q, 1);
        }
    } else {
        int4 s4 = ((const int4*)ei)[g];
        int4 d4 = ((const int4*)ei)[NE / 4 + g];
        src[0] = s4.x; src[1] = s4.y; src[2] = s4.z; src[3] = s4.w;
        dst[0] = d4.x; dst[1] = d4.y; dst[2] = d4.z; dst[3] = d4.w;
    }
    int4 r4 = ((const int4*)g_rank)[g];
    rk[0] = r4.x; rk[1] = r4.y; rk[2] = r4.z; rk[3] = r4.w;
    int pos[4];
#pragma unroll
    for (int q = 0; q < 4; q++) {
        int part = (e0 + q) & (NPART - 1);
        pos[q] = g_cur[part * NN + dst[q]] + rk[q];
    }
#pragma unroll
    for (int q = 0; q < 4; q++) g_csrc[pos[q]] = src[q];
}

// ---------------- GEMM: f32x2 with ROW-PAIR packing + fused logits + fp16 xl ----------------
// acc[i][j] = f32x2 of (row r0+2i, row r0+2i+1) at col c0+j.
// x row-pairs come packed directly out of the transposed xs tile (no dup movs);
// only the 4 W column scalars get duplicated per k (4 movs vs 16 before).
__global__ __launch_bounds__(256, 2) void k_gemm(const float* __restrict__ x,
                                                 const float* __restrict__ W,
                                                 const float* __restrict__ att_src,
                                                 const float* __restrict__ att_dst) {
    __shared__ float xs[32][136];   // [k][row], padded
    __shared__ float ws[32][132];   // [k][col], padded
    int tid = threadIdx.x;
    int lane = tid & 31;
    int row0 = blockIdx.x * 128;
    int r0 = (tid >> 5) * 16;
    int c0 = lane * 4;

    unsigned long long acc[8][4];
#pragma unroll
    for (int i = 0; i < 8; i++)
#pragma unroll
        for (int j = 0; j < 4; j++) acc[i][j] = 0ull;

#pragma unroll 1
    for (int kk = 0; kk < 128; kk += 32) {
        {   // W tile: 32 k-rows x 128 cols
            int lk = tid >> 3;
            int lc = (tid & 7) * 16;
            const float4* wp = (const float4*)(W + (size_t)(kk + lk) * 128 + lc);
            float4* q = (float4*)&ws[lk][lc];
            q[0] = wp[0]; q[1] = wp[1]; q[2] = wp[2]; q[3] = wp[3];
        }
        {   // x tile: 128 rows x 32 k, stored transposed
            int lr = tid >> 1;
            int k0 = (tid & 1) * 16;
            int grow = row0 + lr; if (grow >= NN) grow = NN - 1;
            const float* xp = x + (size_t)grow * 128 + kk + k0;
            float4 a = *(const float4*)xp;
            float4 b = *(const float4*)(xp + 4);
            float4 c = *(const float4*)(xp + 8);
            float4 d = *(const float4*)(xp + 12);
            xs[k0 + 0][lr] = a.x;  xs[k0 + 1][lr] = a.y;
            xs[k0 + 2][lr] = a.z;  xs[k0 + 3][lr] = a.w;
            xs[k0 + 4][lr] = b.x;  xs[k0 + 5][lr] = b.y;
            xs[k0 + 6][lr] = b.z;  xs[k0 + 7][lr] = b.w;
            xs[k0 + 8][lr] = c.x;  xs[k0 + 9][lr] = c.y;
            xs[k0 + 10][lr] = c.z; xs[k0 + 11][lr] = c.w;
            xs[k0 + 12][lr] = d.x; xs[k0 + 13][lr] = d.y;
            xs[k0 + 14][lr] = d.z; xs[k0 + 15][lr] = d.w;
        }
        __syncthreads();
#pragma unroll 4
        for (int k = 0; k < 32; k++) {
            // 8 row-pairs, packed straight from smem (16B-aligned: r0 mult of 16, row 544B)
            ulonglong2 xpA = *(const ulonglong2*)&xs[k][r0];        // pairs 0,1
            ulonglong2 xpB = *(const ulonglong2*)&xs[k][r0 + 4];    // pairs 2,3
            ulonglong2 xpC = *(const ulonglong2*)&xs[k][r0 + 8];    // pairs 4,5
            ulonglong2 xpD = *(const ulonglong2*)&xs[k][r0 + 12];   // pairs 6,7
            float4 wv = *(const float4*)&ws[k][c0];
            unsigned long long wd0 = pk2(wv.x), wd1 = pk2(wv.y);
            unsigned long long wd2 = pk2(wv.z), wd3 = pk2(wv.w);
            unsigned long long xp[8] = {xpA.x, xpA.y, xpB.x, xpB.y,
                                        xpC.x, xpC.y, xpD.x, xpD.y};
#pragma unroll
            for (int i = 0; i < 8; i++) {
                FMA2(acc[i][0], xp[i], wd0, acc[i][0]);
                FMA2(acc[i][1], xp[i], wd1, acc[i][1]);
                FMA2(acc[i][2], xp[i], wd2, acc[i][2]);
                FMA2(acc[i][3], xp[i], wd3, acc[i][3]);
            }
        }
        __syncthreads();
    }

    // epilogue: fp16 xl + attention logits scaled by log2(e)
    float4 asv = ((const float4*)att_src)[lane];
    float4 adv = ((const float4*)att_dst)[lane];
    int head = lane >> 2;
#pragma unroll
    for (int i = 0; i < 8; i++) {
        float a0, b0, a1, b1, a2, b2, a3, b3;   // a*=even row, b*=odd row
        upk2(acc[i][0], a0, b0); upk2(acc[i][1], a1, b1);
        upk2(acc[i][2], a2, b2); upk2(acc[i][3], a3, b3);
#pragma unroll
        for (int par = 0; par < 2; par++) {
            float o0 = par ? b0 : a0, o1 = par ? b1 : a1;
            float o2 = par ? b2 : a2, o3 = par ? b3 : a3;
            int r = row0 + r0 + 2 * i + par;
            float ps = o0 * asv.x + o1 * asv.y + o2 * asv.z + o3 * asv.w;
            float pd = o0 * adv.x + o1 * adv.y + o2 * adv.z + o3 * adv.w;
            ps += __shfl_xor_sync(0xffffffffu, ps, 1);
            ps += __shfl_xor_sync(0xffffffffu, ps, 2);
            pd += __shfl_xor_sync(0xffffffffu, pd, 1);
            pd += __shfl_xor_sync(0xffffffffu, pd, 2);
            if (r < NN) {
                __half2 p0 = __float22half2_rn(make_float2(o0, o1));
                __half2 p1 = __float22half2_rn(make_float2(o2, o3));
                uint2 u;
                u.x = *(unsigned int*)&p0;
                u.y = *(unsigned int*)&p1;
                ((uint2*)g_xlh)[(size_t)r * 32 + lane] = u;
                if ((lane & 3) == 0) {
                    g_asrc[r * 8 + head] = ps * LOG2E;
                    g_adst[r * 8 + head] = pd * LOG2E;
                }
            }
        }
    }
}

// ---------------- warp-per-dst aggregation: 2 edges/warp, 16 lanes/edge ----------------
__global__ __launch_bounds__(256) void k_agg(const float* __restrict__ bias) {
    __shared__ float ss[8][136];
    __shared__ float sq[8][136];
    int g = blockIdx.x * blockDim.x + threadIdx.x;
    int w = g >> 5;
    int lane = g & 31;
    int wid = threadIdx.x >> 5;
    int half = lane >> 4;      // which edge of the pair
    int l = lane & 15;         // position within edge: 8 channels
    int h = l >> 1;            // head of channels 8l..8l+7

    float a0 = 0.f, a1 = 0.f, a2 = 0.f, a3 = 0.f;
    float a4 = 0.f, a5 = 0.f, a6 = 0.f, a7 = 0.f;
    float o0 = 0.f, o1 = 0.f, o2 = 0.f, o3 = 0.f;
    float o4 = 0.f, o5 = 0.f, o6 = 0.f, o7 = 0.f;

    if (w < NN) {
        int start = g_rowptr[w], end = g_rowptr[w + 1];
        float adst = g_adst[w * 8 + h];
        float denom = 0.f;
        const uint4* xlp = (const uint4*)g_xlh;   // row = 16 uint4

        for (int base = start; base < end; base += 32) {
            int idx = base + lane;
            int mysrc = (idx < end) ? g_csrc[idx] : 0;
            int cnt = end - base; if (cnt > 32) cnt = 32;
#pragma unroll 2
            for (int j = 0; j < cnt; j += 2) {
                int myj = j + half;                                   // lanes 0-15: j, 16-31: j+1
                int src = __shfl_sync(0xffffffffu, mysrc, myj);       // per-lane source index
                float e = g_asrc[src * 8 + h] + adst;
                e = fmaxf(e, 0.2f * e);                               // leaky relu (pre-scaled)
                float wq = ex2f(e);
                wq = (myj < cnt) ? wq : 0.f;
                uint4 u = xlp[(size_t)src * 16 + l];
                float2 f;
                f = __half22float2(*(__half2*)&u.x);
                a0 = fmaf(wq, f.x, a0); a1 = fmaf(wq, f.y, a1);
                f = __half22float2(*(__half2*)&u.y);
                a2 = fmaf(wq, f.x, a2); a3 = fmaf(wq, f.y, a3);
                f = __half22float2(*(__half2*)&u.z);
                a4 = fmaf(wq, f.x, a4); a5 = fmaf(wq, f.y, a5);
                f = __half22float2(*(__half2*)&u.w);
                a6 = fmaf(wq, f.x, a6); a7 = fmaf(wq, f.y, a7);
                denom += wq;
            }
        }
        // merge the two edge-parity halves (lane l pairs with lane l+16)
        denom += __shfl_xor_sync(0xffffffffu, denom, 16);
        a0 += __shfl_xor_sync(0xffffffffu, a0, 16);
        a1 += __shfl_xor_sync(0xffffffffu, a1, 16);
        a2 += __shfl_xor_sync(0xffffffffu, a2, 16);
        a3 += __shfl_xor_sync(0xffffffffu, a3, 16);
        a4 += __shfl_xor_sync(0xffffffffu, a4, 16);
        a5 += __shfl_xor_sync(0xffffffffu, a5, 16);
        a6 += __shfl_xor_sync(0xffffffffu, a6, 16);
        a7 += __shfl_xor_sync(0xffffffffu, a7, 16);
        float inv = 1.f / (denom + 1e-16f);
        float4 b0 = ((const float4*)bias)[l * 2];
        float4 b1 = ((const float4*)bias)[l * 2 + 1];
        o0 = fmaf(a0, inv, b0.x); o1 = fmaf(a1, inv, b0.y);
        o2 = fmaf(a2, inv, b0.z); o3 = fmaf(a3, inv, b0.w);
        o4 = fmaf(a4, inv, b1.x); o5 = fmaf(a5, inv, b1.y);
        o6 = fmaf(a6, inv, b1.z); o7 = fmaf(a7, inv, b1.w);
        if (half == 0) {
            float4 v0 = {o0, o1, o2, o3};
            float4 v1 = {o4, o5, o6, o7};
            ((float4*)g_h)[(size_t)w * 32 + l * 2] = v0;
            ((float4*)g_h)[(size_t)w * 32 + l * 2 + 1] = v1;
        }
    }

    // fused BN partial stats: half-0 lanes cover all 128 channels of this warp's node
    if (half == 0) {
        float4 v0 = {o0, o1, o2, o3};
        float4 v1 = {o4, o5, o6, o7};
        float4 q0 = {o0 * o0, o1 * o1, o2 * o2, o3 * o3};
        float4 q1 = {o4 * o4, o5 * o5, o6 * o6, o7 * o7};
        *(float4*)&ss[wid][l * 8] = v0;
        *(float4*)&ss[wid][l * 8 + 4] = v1;
        *(float4*)&sq[wid][l * 8] = q0;
        *(float4*)&sq[wid][l * 8 + 4] = q1;
    }
    __syncthreads();
    int tid = threadIdx.x;
    if (tid < 128) {
        float s = 0.f, q = 0.f;
#pragma unroll
        for (int ww = 0; ww < 8; ww++) { s += ss[ww][tid]; q += sq[ww][tid]; }
        int slot = blockIdx.x & (NSLOT - 1);
        atomicAdd(&g_ps1[slot * 128 + tid], s);
        atomicAdd(&g_ps2[slot * 128 + tid], q);
    }
}

// ---------------- BN params ----------------
__global__ void k_bnp(const float* __restrict__ gamma,
                      const float* __restrict__ beta) {
    int c = threadIdx.x;
    double s = 0.0, q = 0.0;
    for (int b = 0; b < NSLOT; b++) {
        s += (double)g_ps1[b * 128 + c];
        q += (double)g_ps2[b * 128 + c];
    }
    double mean_d = s / (double)NN;
    double var_d = q / (double)NN - mean_d * mean_d;
    float sc = gamma[c] * rsqrtf((float)var_d + 1e-5f);
    g_scale[c] = sc;
    g_shift[c] = beta[c] - (float)mean_d * sc;
}

// ---------------- normalize + ReLU + residual + next-call housekeeping ----------------
__global__ void k_final(const float* __restrict__ x, float* __restrict__ out,
                        const unsigned int* __restrict__ ei) {
    int g = blockIdx.x * blockDim.x + threadIdx.x;   // NN*32 float4s
    if (g < NPART * NN) g_deg[g] = 0;
    if (g < NSLOT * 128) { g_ps1[g] = 0.f; g_ps2[g] = 0.f; }
    if (g == 0) g_is64 = detect64(ei);
    if (g >= NN * 32) return;
    int l = g & 31;
    float4 hv = ((const float4*)g_h)[g];
    float4 xv = ((const float4*)x)[g];
    float4 sc = ((const float4*)g_scale)[l];
    float4 sh = ((const float4*)g_shift)[l];
    float4 o;
    o.x = xv.x + fmaxf(0.f, fmaf(hv.x, sc.x, sh.x));
    o.y = xv.y + fmaxf(0.f, fmaf(hv.y, sc.y, sh.y));
    o.z = xv.z + fmaxf(0.f, fmaf(hv.z, sc.z, sh.z));
    o.w = xv.w + fmaxf(0.f, fmaf(hv.w, sc.w, sh.w));
    ((float4*)out)[g] = o;
}

// ---------------- launch: CSR build forked onto a side stream, overlapped with GEMM --------
extern "C" void kernel_launch(void* const* d_in, const int* in_sizes, int n_in,
                              void* d_out, int out_size) {
    const float* x       = (const float*)d_in[0];
    const void*  ei      = d_in[1];
    const float* W       = (const float*)d_in[2];
    const float* att_src = (const float*)d_in[3];
    const float* att_dst = (const float*)d_in[4];
    const float* bias    = (const float*)d_in[5];
    const float* gamma   = (const float*)d_in[6];
    const float* beta    = (const float*)d_in[7];
    float* out = (float*)d_out;
    (void)in_sizes; (void)n_in; (void)out_size;

    const int WB = (NN * 32 + 255) / 256;     // 6250

    // Fresh fork/join objects each call (kernel_launch runs only a few times;
    // no device memory involved, no static guards, graph-capture-legal pattern).
    cudaStream_t sB;
    cudaEvent_t eF, eJ;
    cudaStreamCreateWithFlags(&sB, cudaStreamNonBlocking);
    cudaEventCreateWithFlags(&eF, cudaEventDisableTiming);
    cudaEventCreateWithFlags(&eJ, cudaEventDisableTiming);

    cudaEventRecord(eF, 0);                  // fork from the (captured) main stream
    cudaStreamWaitEvent(sB, eF, 0);

    // side stream: CSR build (independent of GEMM)
    k_hist <<<(NE / 2 + 255) / 256, 256, 0, sB>>>(ei);
    k_scan <<<1, 1024, 0, sB>>>();
    k_fill <<<(NE / 4 + 255) / 256, 256, 0, sB>>>(ei);
    cudaEventRecord(eJ, sB);

    // main stream: GEMM concurrently
    k_gemm <<<(NN + 127) / 128, 256>>>(x, W, att_src, att_dst);

    cudaStreamWaitEvent(0, eJ, 0);           // join
    k_agg  <<<WB, 256>>>(bias);
    k_bnp  <<<1, 128>>>(gamma, beta);
    k_final<<<WB, 256>>>(x, out, (const unsigned int*)ei);
}

// round 14
// speedup vs baseline: 2.1581x; 1.0687x over previous
#include <cuda_runtime.h>
#include <cuda_fp16.h>
#include <math.h>

#define NN 50000
#define NE 1600000
#define DD 128
#define HH 8
#define NPART 8
#define NSLOT 64
#define LOG2E 1.44269504088896f

// ---------------- scratch (no allocations allowed) ----------------
__device__ __half2 g_xlh[NN * 64];     // x @ W in fp16
__device__ float  g_h[NN * DD];        // pre-BN output
__device__ float  g_asrc[NN * HH];     // pre-scaled by log2(e)
__device__ float  g_adst[NN * HH];     // pre-scaled by log2(e)
__device__ int    g_deg[NPART * NN];   // zero at load; re-zeroed by k_final each call
__device__ int    g_cur[NPART * NN];
__device__ int    g_rank[NE];
__device__ int    g_rowptr[NN + 1];
__device__ int    g_csrc[NE];
__device__ float  g_ps1[NSLOT * 128];  // BN partials (zeroed by k_final)
__device__ float  g_ps2[NSLOT * 128];
__device__ float  g_scale[DD];
__device__ float  g_shift[DD];
__device__ int    g_is64 = -1;         // first call self-detects

// ---------------- helpers ----------------
#define FMA2(d, a, b, c) \
    asm("fma.rn.f32x2 %0, %1, %2, %3;" : "=l"(d) : "l"(a), "l"(b), "l"(c))

__device__ __forceinline__ unsigned long long pk2(float v) {
    unsigned long long r;
    unsigned int u = __float_as_uint(v);
    asm("mov.b64 %0, {%1, %2};" : "=l"(r) : "r"(u), "r"(u));
    return r;
}
__device__ __forceinline__ void upk2(unsigned long long v, float& lo, float& hi) {
    unsigned int a, b;
    asm("mov.b64 {%0, %1}, %2;" : "=r"(a), "=r"(b) : "l"(v));
    lo = __uint_as_float(a);
    hi = __uint_as_float(b);
}
__device__ __forceinline__ float ex2f(float x) {          // guaranteed single MUFU
    float y;
    asm("ex2.approx.ftz.f32 %0, %1;" : "=f"(y) : "f"(x));
    return y;
}

__device__ __forceinline__ int detect64(const unsigned int* w) {
    int is64 = 1;
    for (int j = 1; j < 64; j += 2)
        if (w[j] != 0u) { is64 = 0; break; }
    return is64;
}

__device__ __forceinline__ int edge_val(const void* ei, long long flat, int is64) {
    if (is64) return (int)((const long long*)ei)[flat];
    return ((const int*)ei)[flat];
}

// ---------------- hist: 2 edges/thread, rank recording + 8-way partials ----------------
__global__ void k_hist(const void* __restrict__ ei) {
    int g = blockIdx.x * blockDim.x + threadIdx.x;   // NE/2 threads
    if (g >= NE / 2) return;
    int is64 = g_is64;
    if (is64 < 0) is64 = detect64((const unsigned int*)ei);   // call-1 self-detect
    int e0 = g * 2;
    int d0, d1;
    if (is64) {
        d0 = edge_val(ei, (long long)NE + e0, 1);
        d1 = edge_val(ei, (long long)NE + e0 + 1, 1);
    } else {
        int2 dd = ((const int2*)ei)[NE / 2 + g];
        d0 = dd.x; d1 = dd.y;
    }
    int p0 = e0 & (NPART - 1);
    int p1 = (e0 + 1) & (NPART - 1);
    int r0 = atomicAdd(&g_deg[p0 * NN + d0], 1);
    int r1 = atomicAdd(&g_deg[p1 * NN + d1], 1);
    *(int2*)&g_rank[e0] = make_int2(r0, r1);
}

// ---------------- scan: 4 nodes/thread, int4 vectorized ----------------
__global__ void k_scan() {
    __shared__ int warpsum[32];
    __shared__ int carry;
    int tid = threadIdx.x, lane = tid & 31, wid = tid >> 5;
    if (tid == 0) { carry = 0; g_rowptr[0] = 0; }
    __syncthreads();
    for (int base = 0; base < NN; base += 4096) {
        int i0 = base + tid * 4;
        bool ok = i0 < NN;                    // NN % 4 == 0
        int4 d[NPART];
        int v0 = 0, v1 = 0, v2 = 0, v3 = 0;
#pragma unroll
        for (int p = 0; p < NPART; p++) {
            d[p] = ok ? *(const int4*)&g_deg[p * NN + i0] : make_int4(0, 0, 0, 0);
            v0 += d[p].x; v1 += d[p].y; v2 += d[p].z; v3 += d[p].w;
        }
        int v = v0 + v1 + v2 + v3;
        int s = v;
#pragma unroll
        for (int off = 1; off < 32; off <<= 1) {
            int t = __shfl_up_sync(0xffffffffu, s, off);
            if (lane >= off) s += t;
        }
        if (lane == 31) warpsum[wid] = s;
        __syncthreads();
        if (wid == 0) {
            int ws = warpsum[lane];
            int ss = ws;
#pragma unroll
            for (int off = 1; off < 32; off <<= 1) {
                int t = __shfl_up_sync(0xffffffffu, ss, off);
                if (lane >= off) ss += t;
            }
            warpsum[lane] = ss - ws;
        }
        __syncthreads();
        int incl = s + warpsum[wid] + carry;
        if (ok) {
            int b0 = incl - v;
            int b1 = b0 + v0, b2 = b1 + v1, b3 = b2 + v2;
            g_rowptr[i0 + 1] = b1; g_rowptr[i0 + 2] = b2;
            g_rowptr[i0 + 3] = b3; g_rowptr[i0 + 4] = b3 + v3;
            int c0 = b0, c1 = b1, c2 = b2, c3 = b3;
#pragma unroll
            for (int p = 0; p < NPART; p++) {
                *(int4*)&g_cur[p * NN + i0] = make_int4(c0, c1, c2, c3);
                c0 += d[p].x; c1 += d[p].y; c2 += d[p].z; c3 += d[p].w;
            }
        }
        __syncthreads();
        if (tid == 1023) carry = incl;
        __syncthreads();
    }
}

// ---------------- fill: 4 edges/thread, no atomics ----------------
__global__ void k_fill(const void* __restrict__ ei) {
    int g = blockIdx.x * blockDim.x + threadIdx.x;   // NE/4 threads
    if (g >= NE / 4) return;
    int is64 = g_is64;
    if (is64 < 0) is64 = detect64((const unsigned int*)ei);
    int e0 = g * 4;
    int src[4], dst[4], rk[4];
    if (is64) {
#pragma unroll
        for (int q = 0; q < 4; q++) {
            src[q] = edge_val(ei, e0 + q, 1);
            dst[q] = edge_val(ei, (long long)NE + e0 + q, 1);
        }
    } else {
        int4 s4 = ((const int4*)ei)[g];
        int4 d4 = ((const int4*)ei)[NE / 4 + g];
        src[0] = s4.x; src[1] = s4.y; src[2] = s4.z; src[3] = s4.w;
        dst[0] = d4.x; dst[1] = d4.y; dst[2] = d4.z; dst[3] = d4.w;
    }
    int4 r4 = ((const int4*)g_rank)[g];
    rk[0] = r4.x; rk[1] = r4.y; rk[2] = r4.z; rk[3] = r4.w;
    int pos[4];
#pragma unroll
    for (int q = 0; q < 4; q++) {
        int part = (e0 + q) & (NPART - 1);
        pos[q] = g_cur[part * NN + dst[q]] + rk[q];
    }
#pragma unroll
    for (int q = 0; q < 4; q++) g_csrc[pos[q]] = src[q];
}

// ---------------- GEMM: 512 threads, 4 row-pairs x 4 cols/thread, f32x2 ----------------
// 128x128 block tile, 16 warps; warp w owns rows w*8..w*8+7, lane owns cols lane*4..+3.
__global__ __launch_bounds__(512, 2) void k_gemm(const float* __restrict__ x,
                                                 const float* __restrict__ W,
                                                 const float* __restrict__ att_src,
                                                 const float* __restrict__ att_dst) {
    __shared__ float xs[32][136];   // [k][row], padded
    __shared__ float ws[32][132];   // [k][col], padded
    int tid = threadIdx.x;
    int lane = tid & 31;
    int row0 = blockIdx.x * 128;
    int r0 = (tid >> 5) * 8;        // 8 rows = 4 pairs per warp
    int c0 = lane * 4;

    unsigned long long acc[4][4];
#pragma unroll
    for (int i = 0; i < 4; i++)
#pragma unroll
        for (int j = 0; j < 4; j++) acc[i][j] = 0ull;

#pragma unroll 1
    for (int kk = 0; kk < 128; kk += 32) {
        {   // W tile: 32 k-rows x 128 cols; 8 floats/thread
            int lk = tid >> 4;
            int lc = (tid & 15) * 8;
            const float4* wp = (const float4*)(W + (size_t)(kk + lk) * 128 + lc);
            float4* q = (float4*)&ws[lk][lc];
            q[0] = wp[0]; q[1] = wp[1];
        }
        {   // x tile: 128 rows x 32 k, transposed; 8 k-values/thread
            int lr = tid >> 2;
            int k0 = (tid & 3) * 8;
            int grow = row0 + lr; if (grow >= NN) grow = NN - 1;
            const float* xp = x + (size_t)grow * 128 + kk + k0;
            float4 a = *(const float4*)xp;
            float4 b = *(const float4*)(xp + 4);
            xs[k0 + 0][lr] = a.x; xs[k0 + 1][lr] = a.y;
            xs[k0 + 2][lr] = a.z; xs[k0 + 3][lr] = a.w;
            xs[k0 + 4][lr] = b.x; xs[k0 + 5][lr] = b.y;
            xs[k0 + 6][lr] = b.z; xs[k0 + 7][lr] = b.w;
        }
        __syncthreads();
#pragma unroll 2
        for (int k = 0; k < 32; k++) {
            ulonglong2 xpA = *(const ulonglong2*)&xs[k][r0];      // pairs 0,1
            ulonglong2 xpB = *(const ulonglong2*)&xs[k][r0 + 4];  // pairs 2,3
            float4 wv = *(const float4*)&ws[k][c0];
            unsigned long long wd0 = pk2(wv.x), wd1 = pk2(wv.y);
            unsigned long long wd2 = pk2(wv.z), wd3 = pk2(wv.w);
            unsigned long long xp[4] = {xpA.x, xpA.y, xpB.x, xpB.y};
#pragma unroll
            for (int i = 0; i < 4; i++) {
                FMA2(acc[i][0], xp[i], wd0, acc[i][0]);
                FMA2(acc[i][1], xp[i], wd1, acc[i][1]);
                FMA2(acc[i][2], xp[i], wd2, acc[i][2]);
                FMA2(acc[i][3], xp[i], wd3, acc[i][3]);
            }
        }
        __syncthreads();
    }

    // epilogue: fp16 xl + attention logits scaled by log2(e)
    float4 asv = ((const float4*)att_src)[lane];
    float4 adv = ((const float4*)att_dst)[lane];
    int head = lane >> 2;
#pragma unroll
    for (int i = 0; i < 4; i++) {
        float a0, b0, a1, b1, a2, b2, a3, b3;   // a*=even row, b*=odd row
        upk2(acc[i][0], a0, b0); upk2(acc[i][1], a1, b1);
        upk2(acc[i][2], a2, b2); upk2(acc[i][3], a3, b3);
#pragma unroll
        for (int par = 0; par < 2; par++) {
            float o0 = par ? b0 : a0, o1 = par ? b1 : a1;
            float o2 = par ? b2 : a2, o3 = par ? b3 : a3;
            int r = row0 + r0 + 2 * i + par;
            float ps = o0 * asv.x + o1 * asv.y + o2 * asv.z + o3 * asv.w;
            float pd = o0 * adv.x + o1 * adv.y + o2 * adv.z + o3 * adv.w;
            ps += __shfl_xor_sync(0xffffffffu, ps, 1);
            ps += __shfl_xor_sync(0xffffffffu, ps, 2);
            pd += __shfl_xor_sync(0xffffffffu, pd, 1);
            pd += __shfl_xor_sync(0xffffffffu, pd, 2);
            if (r < NN) {
                __half2 p0 = __float22half2_rn(make_float2(o0, o1));
                __half2 p1 = __float22half2_rn(make_float2(o2, o3));
                uint2 u;
                u.x = *(unsigned int*)&p0;
                u.y = *(unsigned int*)&p1;
                ((uint2*)g_xlh)[(size_t)r * 32 + lane] = u;
                if ((lane & 3) == 0) {
                    g_asrc[r * 8 + head] = ps * LOG2E;
                    g_adst[r * 8 + head] = pd * LOG2E;
                }
            }
        }
    }
}

// ---------------- warp-per-dst aggregation: 2 edges/warp, broadcast csrc loads ----------------
__global__ __launch_bounds__(256) void k_agg(const float* __restrict__ bias) {
    __shared__ float ss[8][136];
    __shared__ float sq[8][136];
    int g = blockIdx.x * blockDim.x + threadIdx.x;
    int w = g >> 5;
    int lane = g & 31;
    int wid = threadIdx.x >> 5;
    int half = lane >> 4;      // which edge of the pair
    int l = lane & 15;         // position within edge: 8 channels
    int h = l >> 1;            // head of channels 8l..8l+7

    float a0 = 0.f, a1 = 0.f, a2 = 0.f, a3 = 0.f;
    float a4 = 0.f, a5 = 0.f, a6 = 0.f, a7 = 0.f;
    float o0 = 0.f, o1 = 0.f, o2 = 0.f, o3 = 0.f;
    float o4 = 0.f, o5 = 0.f, o6 = 0.f, o7 = 0.f;

    if (w < NN) {
        int start = g_rowptr[w], end = g_rowptr[w + 1];
        float adst = g_adst[w * 8 + h];
        float denom = 0.f;
        const uint4* xlp = (const uint4*)g_xlh;   // row = 16 uint4

#pragma unroll 2
        for (int j = start; j < end; j += 2) {
            int myj = j + half;                       // lanes 0-15: j, 16-31: j+1
            bool act = myj < end;
            int idx = act ? myj : end - 1;
            int src = __ldg(&g_csrc[idx]);            // broadcast LDG (same L1 line ~16 iters)
            float e = __ldg(&g_asrc[src * 8 + h]) + adst;
            e = fmaxf(e, 0.2f * e);                   // leaky relu (pre-scaled by log2e)
            float wq = ex2f(e);
            wq = act ? wq : 0.f;
            uint4 u = __ldg(&xlp[(size_t)src * 16 + l]);
            float2 f;
            f = __half22float2(*(__half2*)&u.x);
            a0 = fmaf(wq, f.x, a0); a1 = fmaf(wq, f.y, a1);
            f = __half22float2(*(__half2*)&u.y);
            a2 = fmaf(wq, f.x, a2); a3 = fmaf(wq, f.y, a3);
            f = __half22float2(*(__half2*)&u.z);
            a4 = fmaf(wq, f.x, a4); a5 = fmaf(wq, f.y, a5);
            f = __half22float2(*(__half2*)&u.w);
            a6 = fmaf(wq, f.x, a6); a7 = fmaf(wq, f.y, a7);
            denom += wq;
        }
        // merge the two edge-parity halves (lane l pairs with lane l+16)
        denom += __shfl_xor_sync(0xffffffffu, denom, 16);
        a0 += __shfl_xor_sync(0xffffffffu, a0, 16);
        a1 += __shfl_xor_sync(0xffffffffu, a1, 16);
        a2 += __shfl_xor_sync(0xffffffffu, a2, 16);
        a3 += __shfl_xor_sync(0xffffffffu, a3, 16);
        a4 += __shfl_xor_sync(0xffffffffu, a4, 16);
        a5 += __shfl_xor_sync(0xffffffffu, a5, 16);
        a6 += __shfl_xor_sync(0xffffffffu, a6, 16);
        a7 += __shfl_xor_sync(0xffffffffu, a7, 16);
        float inv = 1.f / (denom + 1e-16f);
        float4 b0 = ((const float4*)bias)[l * 2];
        float4 b1 = ((const float4*)bias)[l * 2 + 1];
        o0 = fmaf(a0, inv, b0.x); o1 = fmaf(a1, inv, b0.y);
        o2 = fmaf(a2, inv, b0.z); o3 = fmaf(a3, inv, b0.w);
        o4 = fmaf(a4, inv, b1.x); o5 = fmaf(a5, inv, b1.y);
        o6 = fmaf(a6, inv, b1.z); o7 = fmaf(a7, inv, b1.w);
        if (half == 0) {
            float4 v0 = {o0, o1, o2, o3};
            float4 v1 = {o4, o5, o6, o7};
            ((float4*)g_h)[(size_t)w * 32 + l * 2] = v0;
            ((float4*)g_h)[(size_t)w * 32 + l * 2 + 1] = v1;
        }
    }

    // fused BN partial stats: half-0 lanes cover all 128 channels of this warp's node
    if (half == 0) {
        float4 v0 = {o0, o1, o2, o3};
        float4 v1 = {o4, o5, o6, o7};
        float4 q0 = {o0 * o0, o1 * o1, o2 * o2, o3 * o3};
        float4 q1 = {o4 * o4, o5 * o5, o6 * o6, o7 * o7};
        *(float4*)&ss[wid][l * 8] = v0;
        *(float4*)&ss[wid][l * 8 + 4] = v1;
        *(float4*)&sq[wid][l * 8] = q0;
        *(float4*)&sq[wid][l * 8 + 4] = q1;
    }
    __syncthreads();
    int tid = threadIdx.x;
    if (tid < 128) {
        float s = 0.f, q = 0.f;
#pragma unroll
        for (int ww = 0; ww < 8; ww++) { s += ss[ww][tid]; q += sq[ww][tid]; }
        int slot = blockIdx.x & (NSLOT - 1);
        atomicAdd(&g_ps1[slot * 128 + tid], s);
        atomicAdd(&g_ps2[slot * 128 + tid], q);
    }
}

// ---------------- BN params ----------------
__global__ void k_bnp(const float* __restrict__ gamma,
                      const float* __restrict__ beta) {
    int c = threadIdx.x;
    double s = 0.0, q = 0.0;
    for (int b = 0; b < NSLOT; b++) {
        s += (double)g_ps1[b * 128 + c];
        q += (double)g_ps2[b * 128 + c];
    }
    double mean_d = s / (double)NN;
    double var_d = q / (double)NN - mean_d * mean_d;
    float sc = gamma[c] * rsqrtf((float)var_d + 1e-5f);
    g_scale[c] = sc;
    g_shift[c] = beta[c] - (float)mean_d * sc;
}

// ---------------- normalize + ReLU + residual + next-call housekeeping ----------------
__global__ void k_final(const float* __restrict__ x, float* __restrict__ out,
                        const unsigned int* __restrict__ ei) {
    int g = blockIdx.x * blockDim.x + threadIdx.x;   // NN*32 float4s
    if (g < NPART * NN) g_deg[g] = 0;
    if (g < NSLOT * 128) { g_ps1[g] = 0.f; g_ps2[g] = 0.f; }
    if (g == 0) g_is64 = detect64(ei);
    if (g >= NN * 32) return;
    int l = g & 31;
    float4 hv = ((const float4*)g_h)[g];
    float4 xv = ((const float4*)x)[g];
    float4 sc = ((const float4*)g_scale)[l];
    float4 sh = ((const float4*)g_shift)[l];
    float4 o;
    o.x = xv.x + fmaxf(0.f, fmaf(hv.x, sc.x, sh.x));
    o.y = xv.y + fmaxf(0.f, fmaf(hv.y, sc.y, sh.y));
    o.z = xv.z + fmaxf(0.f, fmaf(hv.z, sc.z, sh.z));
    o.w = xv.w + fmaxf(0.f, fmaf(hv.w, sc.w, sh.w));
    ((float4*)out)[g] = o;
}

// ---------------- launch: CSR build forked onto a side stream, overlapped with GEMM --------
extern "C" void kernel_launch(void* const* d_in, const int* in_sizes, int n_in,
                              void* d_out, int out_size) {
    const float* x       = (const float*)d_in[0];
    const void*  ei      = d_in[1];
    const float* W       = (const float*)d_in[2];
    const float* att_src = (const float*)d_in[3];
    const float* att_dst = (const float*)d_in[4];
    const float* bias    = (const float*)d_in[5];
    const float* gamma   = (const float*)d_in[6];
    const float* beta    = (const float*)d_in[7];
    float* out = (float*)d_out;
    (void)in_sizes; (void)n_in; (void)out_size;

    const int WB = (NN * 32 + 255) / 256;     // 6250

    cudaStream_t sB;
    cudaEvent_t eF, eJ;
    cudaStreamCreateWithFlags(&sB, cudaStreamNonBlocking);
    cudaEventCreateWithFlags(&eF, cudaEventDisableTiming);
    cudaEventCreateWithFlags(&eJ, cudaEventDisableTiming);

    cudaEventRecord(eF, 0);                  // fork from the (captured) main stream
    cudaStreamWaitEvent(sB, eF, 0);

    // side stream: CSR build (independent of GEMM)
    k_hist <<<(NE / 2 + 255) / 256, 256, 0, sB>>>(ei);
    k_scan <<<1, 1024, 0, sB>>>();
    k_fill <<<(NE / 4 + 255) / 256, 256, 0, sB>>>(ei);
    cudaEventRecord(eJ, sB);

    // main stream: GEMM concurrently
    k_gemm <<<(NN + 127) / 128, 512>>>(x, W, att_src, att_dst);

    cudaStreamWaitEvent(0, eJ, 0);           // join
    k_agg  <<<WB, 256>>>(bias);
    k_bnp  <<<1, 128>>>(gamma, beta);
    k_final<<<WB, 256>>>(x, out, (const unsigned int*)ei);
}

// round 15
// speedup vs baseline: 2.1888x; 1.0142x over previous
#include <cuda_runtime.h>
#include <cuda_fp16.h>
#include <math.h>

#define NN 50000
#define NE 1600000
#define DD 128
#define HH 8
#define NPART 8
#define NSLOT 64
#define LOG2E 1.44269504088896f

// ---------------- scratch (no allocations allowed) ----------------
__device__ __half2 g_xlh[NN * 64];     // x @ W in fp16
__device__ float  g_h[NN * DD];        // pre-BN output
__device__ float  g_asrc[NN * HH];     // pre-scaled by log2(e)
__device__ float  g_adst[NN * HH];     // pre-scaled by log2(e)
__device__ int    g_deg[NPART * NN];   // zero at load; re-zeroed by k_final each call
__device__ int    g_cur[NPART * NN];
__device__ int    g_rank[NE];
__device__ int    g_rowptr[NN + 1];
__device__ int    g_csrc[NE];
__device__ float  g_ps1[NSLOT * 128];  // BN partials (zeroed by k_final)
__device__ float  g_ps2[NSLOT * 128];
__device__ float  g_scale[DD];
__device__ float  g_shift[DD];
__device__ int    g_is64 = -1;         // first call self-detects

// ---------------- helpers ----------------
#define FMA2(d, a, b, c) \
    asm("fma.rn.f32x2 %0, %1, %2, %3;" : "=l"(d) : "l"(a), "l"(b), "l"(c))

__device__ __forceinline__ unsigned long long pk2(float v) {
    unsigned long long r;
    unsigned int u = __float_as_uint(v);
    asm("mov.b64 %0, {%1, %2};" : "=l"(r) : "r"(u), "r"(u));
    return r;
}
__device__ __forceinline__ void upk2(unsigned long long v, float& lo, float& hi) {
    unsigned int a, b;
    asm("mov.b64 {%0, %1}, %2;" : "=r"(a), "=r"(b) : "l"(v));
    lo = __uint_as_float(a);
    hi = __uint_as_float(b);
}
__device__ __forceinline__ float ex2f(float x) {          // guaranteed single MUFU
    float y;
    asm("ex2.approx.ftz.f32 %0, %1;" : "=f"(y) : "f"(x));
    return y;
}

__device__ __forceinline__ int detect64(const unsigned int* w) {
    int is64 = 1;
    for (int j = 1; j < 64; j += 2)
        if (w[j] != 0u) { is64 = 0; break; }
    return is64;
}

__device__ __forceinline__ int edge_val(const void* ei, long long flat, int is64) {
    if (is64) return (int)((const long long*)ei)[flat];
    return ((const int*)ei)[flat];
}

// ---------------- hist: 2 edges/thread, rank recording + 8-way partials ----------------
__global__ void k_hist(const void* __restrict__ ei) {
    int g = blockIdx.x * blockDim.x + threadIdx.x;   // NE/2 threads
    if (g >= NE / 2) return;
    int is64 = g_is64;
    if (is64 < 0) is64 = detect64((const unsigned int*)ei);   // call-1 self-detect
    int e0 = g * 2;
    int d0, d1;
    if (is64) {
        d0 = edge_val(ei, (long long)NE + e0, 1);
        d1 = edge_val(ei, (long long)NE + e0 + 1, 1);
    } else {
        int2 dd = ((const int2*)ei)[NE / 2 + g];
        d0 = dd.x; d1 = dd.y;
    }
    int p0 = e0 & (NPART - 1);
    int p1 = (e0 + 1) & (NPART - 1);
    int r0 = atomicAdd(&g_deg[p0 * NN + d0], 1);
    int r1 = atomicAdd(&g_deg[p1 * NN + d1], 1);
    *(int2*)&g_rank[e0] = make_int2(r0, r1);
}

// ---------------- scan: 4 nodes/thread, int4 vectorized ----------------
__global__ void k_scan() {
    __shared__ int warpsum[32];
    __shared__ int carry;
    int tid = threadIdx.x, lane = tid & 31, wid = tid >> 5;
    if (tid == 0) { carry = 0; g_rowptr[0] = 0; }
    __syncthreads();
    for (int base = 0; base < NN; base += 4096) {
        int i0 = base + tid * 4;
        bool ok = i0 < NN;                    // NN % 4 == 0
        int4 d[NPART];
        int v0 = 0, v1 = 0, v2 = 0, v3 = 0;
#pragma unroll
        for (int p = 0; p < NPART; p++) {
            d[p] = ok ? *(const int4*)&g_deg[p * NN + i0] : make_int4(0, 0, 0, 0);
            v0 += d[p].x; v1 += d[p].y; v2 += d[p].z; v3 += d[p].w;
        }
        int v = v0 + v1 + v2 + v3;
        int s = v;
#pragma unroll
        for (int off = 1; off < 32; off <<= 1) {
            int t = __shfl_up_sync(0xffffffffu, s, off);
            if (lane >= off) s += t;
        }
        if (lane == 31) warpsum[wid] = s;
        __syncthreads();
        if (wid == 0) {
            int ws = warpsum[lane];
            int ss = ws;
#pragma unroll
            for (int off = 1; off < 32; off <<= 1) {
                int t = __shfl_up_sync(0xffffffffu, ss, off);
                if (lane >= off) ss += t;
            }
            warpsum[lane] = ss - ws;
        }
        __syncthreads();
        int incl = s + warpsum[wid] + carry;
        if (ok) {
            int b0 = incl - v;
            int b1 = b0 + v0, b2 = b1 + v1, b3 = b2 + v2;
            g_rowptr[i0 + 1] = b1; g_rowptr[i0 + 2] = b2;
            g_rowptr[i0 + 3] = b3; g_rowptr[i0 + 4] = b3 + v3;
            int c0 = b0, c1 = b1, c2 = b2, c3 = b3;
#pragma unroll
            for (int p = 0; p < NPART; p++) {
                *(int4*)&g_cur[p * NN + i0] = make_int4(c0, c1, c2, c3);
                c0 += d[p].x; c1 += d[p].y; c2 += d[p].z; c3 += d[p].w;
            }
        }
        __syncthreads();
        if (tid == 1023) carry = incl;
        __syncthreads();
    }
}

// ---------------- fill: 4 edges/thread, no atomics ----------------
__global__ void k_fill(const void* __restrict__ ei) {
    int g = blockIdx.x * blockDim.x + threadIdx.x;   // NE/4 threads
    if (g >= NE / 4) return;
    int is64 = g_is64;
    if (is64 < 0) is64 = detect64((const unsigned int*)ei);
    int e0 = g * 4;
    int src[4], dst[4], rk[4];
    if (is64) {
#pragma unroll
        for (int q = 0; q < 4; q++) {
            src[q] = edge_val(ei, e0 + q, 1);
            dst[q] = edge_val(ei, (long long)NE + e0 + q, 1);
        }
    } else {
        int4 s4 = ((const int4*)ei)[g];
        int4 d4 = ((const int4*)ei)[NE / 4 + g];
        src[0] = s4.x; src[1] = s4.y; src[2] = s4.z; src[3] = s4.w;
        dst[0] = d4.x; dst[1] = d4.y; dst[2] = d4.z; dst[3] = d4.w;
    }
    int4 r4 = ((const int4*)g_rank)[g];
    rk[0] = r4.x; rk[1] = r4.y; rk[2] = r4.z; rk[3] = r4.w;
    int pos[4];
#pragma unroll
    for (int q = 0; q < 4; q++) {
        int part = (e0 + q) & (NPART - 1);
        pos[q] = g_cur[part * NN + dst[q]] + rk[q];
    }
#pragma unroll
    for (int q = 0; q < 4; q++) g_csrc[pos[q]] = src[q];
}

// ---------------- GEMM: 512 threads, 4 row-pairs x 4 cols/thread, f32x2 ----------------
__global__ __launch_bounds__(512, 2) void k_gemm(const float* __restrict__ x,
                                                 const float* __restrict__ W,
                                                 const float* __restrict__ att_src,
                                                 const float* __restrict__ att_dst) {
    __shared__ float xs[32][136];   // [k][row], padded
    __shared__ float ws[32][132];   // [k][col], padded
    int tid = threadIdx.x;
    int lane = tid & 31;
    int row0 = blockIdx.x * 128;
    int r0 = (tid >> 5) * 8;        // 8 rows = 4 pairs per warp
    int c0 = lane * 4;

    unsigned long long acc[4][4];
#pragma unroll
    for (int i = 0; i < 4; i++)
#pragma unroll
        for (int j = 0; j < 4; j++) acc[i][j] = 0ull;

#pragma unroll 1
    for (int kk = 0; kk < 128; kk += 32) {
        {   // W tile: 32 k-rows x 128 cols; 8 floats/thread
            int lk = tid >> 4;
            int lc = (tid & 15) * 8;
            const float4* wp = (const float4*)(W + (size_t)(kk + lk) * 128 + lc);
            float4* q = (float4*)&ws[lk][lc];
            q[0] = wp[0]; q[1] = wp[1];
        }
        {   // x tile: 128 rows x 32 k, transposed; 8 k-values/thread
            int lr = tid >> 2;
            int k0 = (tid & 3) * 8;
            int grow = row0 + lr; if (grow >= NN) grow = NN - 1;
            const float* xp = x + (size_t)grow * 128 + kk + k0;
            float4 a = *(const float4*)xp;
            float4 b = *(const float4*)(xp + 4);
            xs[k0 + 0][lr] = a.x; xs[k0 + 1][lr] = a.y;
            xs[k0 + 2][lr] = a.z; xs[k0 + 3][lr] = a.w;
            xs[k0 + 4][lr] = b.x; xs[k0 + 5][lr] = b.y;
            xs[k0 + 6][lr] = b.z; xs[k0 + 7][lr] = b.w;
        }
        __syncthreads();
#pragma unroll 2
        for (int k = 0; k < 32; k++) {
            ulonglong2 xpA = *(const ulonglong2*)&xs[k][r0];      // pairs 0,1
            ulonglong2 xpB = *(const ulonglong2*)&xs[k][r0 + 4];  // pairs 2,3
            float4 wv = *(const float4*)&ws[k][c0];
            unsigned long long wd0 = pk2(wv.x), wd1 = pk2(wv.y);
            unsigned long long wd2 = pk2(wv.z), wd3 = pk2(wv.w);
            unsigned long long xp[4] = {xpA.x, xpA.y, xpB.x, xpB.y};
#pragma unroll
            for (int i = 0; i < 4; i++) {
                FMA2(acc[i][0], xp[i], wd0, acc[i][0]);
                FMA2(acc[i][1], xp[i], wd1, acc[i][1]);
                FMA2(acc[i][2], xp[i], wd2, acc[i][2]);
                FMA2(acc[i][3], xp[i], wd3, acc[i][3]);
            }
        }
        __syncthreads();
    }

    // epilogue: fp16 xl + attention logits scaled by log2(e)
    float4 asv = ((const float4*)att_src)[lane];
    float4 adv = ((const float4*)att_dst)[lane];
    int head = lane >> 2;
#pragma unroll
    for (int i = 0; i < 4; i++) {
        float a0, b0, a1, b1, a2, b2, a3, b3;   // a*=even row, b*=odd row
        upk2(acc[i][0], a0, b0); upk2(acc[i][1], a1, b1);
        upk2(acc[i][2], a2, b2); upk2(acc[i][3], a3, b3);
#pragma unroll
        for (int par = 0; par < 2; par++) {
            float o0 = par ? b0 : a0, o1 = par ? b1 : a1;
            float o2 = par ? b2 : a2, o3 = par ? b3 : a3;
            int r = row0 + r0 + 2 * i + par;
            float ps = o0 * asv.x + o1 * asv.y + o2 * asv.z + o3 * asv.w;
            float pd = o0 * adv.x + o1 * adv.y + o2 * adv.z + o3 * adv.w;
            ps += __shfl_xor_sync(0xffffffffu, ps, 1);
            ps += __shfl_xor_sync(0xffffffffu, ps, 2);
            pd += __shfl_xor_sync(0xffffffffu, pd, 1);
            pd += __shfl_xor_sync(0xffffffffu, pd, 2);
            if (r < NN) {
                __half2 p0 = __float22half2_rn(make_float2(o0, o1));
                __half2 p1 = __float22half2_rn(make_float2(o2, o3));
                uint2 u;
                u.x = *(unsigned int*)&p0;
                u.y = *(unsigned int*)&p1;
                ((uint2*)g_xlh)[(size_t)r * 32 + lane] = u;
                if ((lane & 3) == 0) {
                    g_asrc[r * 8 + head] = ps * LOG2E;
                    g_adst[r * 8 + head] = pd * LOG2E;
                }
            }
        }
    }
}

// ---------------- warp-per-dst aggregation: lane-private strided walk + prefetch ----------
// lanes 0-15 process edges start, start+2, ...; lanes 16-31 process start+1, start+3, ...
// csrc loads are broadcast within each half-warp; src prefetched one iteration ahead.
__global__ __launch_bounds__(256) void k_agg(const float* __restrict__ bias) {
    __shared__ float ss[8][136];
    __shared__ float sq[8][136];
    int g = blockIdx.x * blockDim.x + threadIdx.x;
    int w = g >> 5;
    int lane = g & 31;
    int wid = threadIdx.x >> 5;
    int half = lane >> 4;      // which edge parity this lane serves
    int l = lane & 15;         // position within edge: 8 channels
    int h = l >> 1;            // head of channels 8l..8l+7

    float a0 = 0.f, a1 = 0.f, a2 = 0.f, a3 = 0.f;
    float a4 = 0.f, a5 = 0.f, a6 = 0.f, a7 = 0.f;
    float o0 = 0.f, o1 = 0.f, o2 = 0.f, o3 = 0.f;
    float o4 = 0.f, o5 = 0.f, o6 = 0.f, o7 = 0.f;

    if (w < NN) {
        int start = g_rowptr[w], end = g_rowptr[w + 1];
        float adst = g_adst[w * 8 + h];
        float denom = 0.f;
        const char* xlb = (const char*)g_xlh + (unsigned)(l * 16);  // lane channel base
        const float* asp = g_asrc + h;

        int j = start + half;                       // lane-private edge stream
        int src_n = (j < end) ? __ldg(&g_csrc[j]) : 0;
#pragma unroll 2
        while (j < end) {
            int src = src_n;
            int jn = j + 2;
            if (jn < end) src_n = __ldg(&g_csrc[jn]);   // prefetch next edge index
            float e = __ldg(asp + src * 8) + adst;
            e = fmaxf(e, 0.2f * e);                     // leaky relu (pre-scaled by log2e)
            float wq = ex2f(e);
            uint4 u = *(const uint4*)(xlb + ((unsigned)src << 8));
            float2 f;
            f = __half22float2(*(__half2*)&u.x);
            a0 = fmaf(wq, f.x, a0); a1 = fmaf(wq, f.y, a1);
            f = __half22float2(*(__half2*)&u.y);
            a2 = fmaf(wq, f.x, a2); a3 = fmaf(wq, f.y, a3);
            f = __half22float2(*(__half2*)&u.z);
            a4 = fmaf(wq, f.x, a4); a5 = fmaf(wq, f.y, a5);
            f = __half22float2(*(__half2*)&u.w);
            a6 = fmaf(wq, f.x, a6); a7 = fmaf(wq, f.y, a7);
            denom += wq;
            j = jn;
        }
        // merge the two edge-parity halves (lane l pairs with lane l+16)
        denom += __shfl_xor_sync(0xffffffffu, denom, 16);
        a0 += __shfl_xor_sync(0xffffffffu, a0, 16);
        a1 += __shfl_xor_sync(0xffffffffu, a1, 16);
        a2 += __shfl_xor_sync(0xffffffffu, a2, 16);
        a3 += __shfl_xor_sync(0xffffffffu, a3, 16);
        a4 += __shfl_xor_sync(0xffffffffu, a4, 16);
        a5 += __shfl_xor_sync(0xffffffffu, a5, 16);
        a6 += __shfl_xor_sync(0xffffffffu, a6, 16);
        a7 += __shfl_xor_sync(0xffffffffu, a7, 16);
        float inv = 1.f / (denom + 1e-16f);
        float4 b0 = ((const float4*)bias)[l * 2];
        float4 b1 = ((const float4*)bias)[l * 2 + 1];
        o0 = fmaf(a0, inv, b0.x); o1 = fmaf(a1, inv, b0.y);
        o2 = fmaf(a2, inv, b0.z); o3 = fmaf(a3, inv, b0.w);
        o4 = fmaf(a4, inv, b1.x); o5 = fmaf(a5, inv, b1.y);
        o6 = fmaf(a6, inv, b1.z); o7 = fmaf(a7, inv, b1.w);
        if (half == 0) {
            float4 v0 = {o0, o1, o2, o3};
            float4 v1 = {o4, o5, o6, o7};
            ((float4*)g_h)[(size_t)w * 32 + l * 2] = v0;
            ((float4*)g_h)[(size_t)w * 32 + l * 2 + 1] = v1;
        }
    }

    // fused BN partial stats: half-0 lanes cover all 128 channels of this warp's node
    if (half == 0) {
        float4 v0 = {o0, o1, o2, o3};
        float4 v1 = {o4, o5, o6, o7};
        float4 q0 = {o0 * o0, o1 * o1, o2 * o2, o3 * o3};
        float4 q1 = {o4 * o4, o5 * o5, o6 * o6, o7 * o7};
        *(float4*)&ss[wid][l * 8] = v0;
        *(float4*)&ss[wid][l * 8 + 4] = v1;
        *(float4*)&sq[wid][l * 8] = q0;
        *(float4*)&sq[wid][l * 8 + 4] = q1;
    }
    __syncthreads();
    int tid = threadIdx.x;
    if (tid < 128) {
        float s = 0.f, q = 0.f;
#pragma unroll
        for (int ww = 0; ww < 8; ww++) { s += ss[ww][tid]; q += sq[ww][tid]; }
        int slot = blockIdx.x & (NSLOT - 1);
        atomicAdd(&g_ps1[slot * 128 + tid], s);
        atomicAdd(&g_ps2[slot * 128 + tid], q);
    }
}

// ---------------- BN params ----------------
__global__ void k_bnp(const float* __restrict__ gamma,
                      const float* __restrict__ beta) {
    int c = threadIdx.x;
    double s = 0.0, q = 0.0;
    for (int b = 0; b < NSLOT; b++) {
        s += (double)g_ps1[b * 128 + c];
        q += (double)g_ps2[b * 128 + c];
    }
    double mean_d = s / (double)NN;
    double var_d = q / (double)NN - mean_d * mean_d;
    float sc = gamma[c] * rsqrtf((float)var_d + 1e-5f);
    g_scale[c] = sc;
    g_shift[c] = beta[c] - (float)mean_d * sc;
}

// ---------------- normalize + ReLU + residual + next-call housekeeping ----------------
__global__ void k_final(const float* __restrict__ x, float* __restrict__ out,
                        const unsigned int* __restrict__ ei) {
    int g = blockIdx.x * blockDim.x + threadIdx.x;   // NN*32 float4s
    if (g < NPART * NN) g_deg[g] = 0;
    if (g < NSLOT * 128) { g_ps1[g] = 0.f; g_ps2[g] = 0.f; }
    if (g == 0) g_is64 = detect64(ei);
    if (g >= NN * 32) return;
    int l = g & 31;
    float4 hv = ((const float4*)g_h)[g];
    float4 xv = ((const float4*)x)[g];
    float4 sc = ((const float4*)g_scale)[l];
    float4 sh = ((const float4*)g_shift)[l];
    float4 o;
    o.x = xv.x + fmaxf(0.f, fmaf(hv.x, sc.x, sh.x));
    o.y = xv.y + fmaxf(0.f, fmaf(hv.y, sc.y, sh.y));
    o.z = xv.z + fmaxf(0.f, fmaf(hv.z, sc.z, sh.z));
    o.w = xv.w + fmaxf(0.f, fmaf(hv.w, sc.w, sh.w));
    ((float4*)out)[g] = o;
}

// ---------------- launch: CSR build forked onto a side stream, overlapped with GEMM --------
extern "C" void kernel_launch(void* const* d_in, const int* in_sizes, int n_in,
                              void* d_out, int out_size) {
    const float* x       = (const float*)d_in[0];
    const void*  ei      = d_in[1];
    const float* W       = (const float*)d_in[2];
    const float* att_src = (const float*)d_in[3];
    const float* att_dst = (const float*)d_in[4];
    const float* bias    = (const float*)d_in[5];
    const float* gamma   = (const float*)d_in[6];
    const float* beta    = (const float*)d_in[7];
    float* out = (float*)d_out;
    (void)in_sizes; (void)n_in; (void)out_size;

    const int WB = (NN * 32 + 255) / 256;     // 6250

    cudaStream_t sB;
    cudaEvent_t eF, eJ;
    cudaStreamCreateWithFlags(&sB, cudaStreamNonBlocking);
    cudaEventCreateWithFlags(&eF, cudaEventDisableTiming);
    cudaEventCreateWithFlags(&eJ, cudaEventDisableTiming);

    cudaEventRecord(eF, 0);                  // fork from the (captured) main stream
    cudaStreamWaitEvent(sB, eF, 0);

    // side stream: CSR build (independent of GEMM)
    k_hist <<<(NE / 2 + 255) / 256, 256, 0, sB>>>(ei);
    k_scan <<<1, 1024, 0, sB>>>();
    k_fill <<<(NE / 4 + 255) / 256, 256, 0, sB>>>(ei);
    cudaEventRecord(eJ, sB);

    // main stream: GEMM concurrently
    k_gemm <<<(NN + 127) / 128, 512>>>(x, W, att_src, att_dst);

    cudaStreamWaitEvent(0, eJ, 0);           // join
    k_agg  <<<WB, 256>>>(bias);
    k_bnp  <<<1, 128>>>(gamma, beta);
    k_final<<<WB, 256>>>(x, out, (const unsigned int*)ei);
}

// round 16
// speedup vs baseline: 2.2251x; 1.0166x over previous
#include <cuda_runtime.h>
#include <cuda_fp16.h>
#include <math.h>

#define NN 50000
#define NE 1600000
#define DD 128
#define HH 8
#define NPART 8
#define NSLOT 64
#define LOG2E 1.44269504088896f

// ---------------- scratch (no allocations allowed) ----------------
__device__ __half2 g_xlh[NN * 64];     // x @ W in fp16
__device__ __half2 g_hh[NN * 64];      // pre-BN output (fp16)
__device__ float  g_asrc[NN * HH];     // pre-scaled by log2(e)
__device__ float  g_adst[NN * HH];     // pre-scaled by log2(e)
__device__ int    g_deg[NPART * NN];   // zero at load; re-zeroed by k_final each call
__device__ int    g_cur[NPART * NN];
__device__ int    g_rank[NE];
__device__ int    g_rowptr[NN + 1];
__device__ int    g_csrc[NE];
__device__ float  g_ps1[NSLOT * 128];  // BN partials (zeroed by k_final)
__device__ float  g_ps2[NSLOT * 128];
__device__ float  g_scale[DD];
__device__ float  g_shift[DD];
__device__ int    g_is64 = -1;         // first call self-detects

// ---------------- helpers ----------------
#define FMA2(d, a, b, c) \
    asm("fma.rn.f32x2 %0, %1, %2, %3;" : "=l"(d) : "l"(a), "l"(b), "l"(c))

__device__ __forceinline__ unsigned long long pk2(float v) {
    unsigned long long r;
    unsigned int u = __float_as_uint(v);
    asm("mov.b64 %0, {%1, %2};" : "=l"(r) : "r"(u), "r"(u));
    return r;
}
__device__ __forceinline__ void upk2(unsigned long long v, float& lo, float& hi) {
    unsigned int a, b;
    asm("mov.b64 {%0, %1}, %2;" : "=r"(a), "=r"(b) : "l"(v));
    lo = __uint_as_float(a);
    hi = __uint_as_float(b);
}
__device__ __forceinline__ float ex2f(float x) {          // guaranteed single MUFU
    float y;
    asm("ex2.approx.ftz.f32 %0, %1;" : "=f"(y) : "f"(x));
    return y;
}
__device__ __forceinline__ unsigned int h2bits(__half2 h) {
    return *(unsigned int*)&h;
}

__device__ __forceinline__ int detect64(const unsigned int* w) {
    int is64 = 1;
    for (int j = 1; j < 64; j += 2)
        if (w[j] != 0u) { is64 = 0; break; }
    return is64;
}

__device__ __forceinline__ int edge_val(const void* ei, long long flat, int is64) {
    if (is64) return (int)((const long long*)ei)[flat];
    return ((const int*)ei)[flat];
}

// ---------------- hist: 2 edges/thread, rank recording + 8-way partials ----------------
__global__ void k_hist(const void* __restrict__ ei) {
    int g = blockIdx.x * blockDim.x + threadIdx.x;   // NE/2 threads
    if (g >= NE / 2) return;
    int is64 = g_is64;
    if (is64 < 0) is64 = detect64((const unsigned int*)ei);   // call-1 self-detect
    int e0 = g * 2;
    int d0, d1;
    if (is64) {
        d0 = edge_val(ei, (long long)NE + e0, 1);
        d1 = edge_val(ei, (long long)NE + e0 + 1, 1);
    } else {
        int2 dd = ((const int2*)ei)[NE / 2 + g];
        d0 = dd.x; d1 = dd.y;
    }
    int p0 = e0 & (NPART - 1);
    int p1 = (e0 + 1) & (NPART - 1);
    int r0 = atomicAdd(&g_deg[p0 * NN + d0], 1);
    int r1 = atomicAdd(&g_deg[p1 * NN + d1], 1);
    *(int2*)&g_rank[e0] = make_int2(r0, r1);
}

// ---------------- scan: 4 nodes/thread, int4 vectorized ----------------
__global__ void k_scan() {
    __shared__ int warpsum[32];
    __shared__ int carry;
    int tid = threadIdx.x, lane = tid & 31, wid = tid >> 5;
    if (tid == 0) { carry = 0; g_rowptr[0] = 0; }
    __syncthreads();
    for (int base = 0; base < NN; base += 4096) {
        int i0 = base + tid * 4;
        bool ok = i0 < NN;                    // NN % 4 == 0
        int4 d[NPART];
        int v0 = 0, v1 = 0, v2 = 0, v3 = 0;
#pragma unroll
        for (int p = 0; p < NPART; p++) {
            d[p] = ok ? *(const int4*)&g_deg[p * NN + i0] : make_int4(0, 0, 0, 0);
            v0 += d[p].x; v1 += d[p].y; v2 += d[p].z; v3 += d[p].w;
        }
        int v = v0 + v1 + v2 + v3;
        int s = v;
#pragma unroll
        for (int off = 1; off < 32; off <<= 1) {
            int t = __shfl_up_sync(0xffffffffu, s, off);
            if (lane >= off) s += t;
        }
        if (lane == 31) warpsum[wid] = s;
        __syncthreads();
        if (wid == 0) {
            int ws = warpsum[lane];
            int ss = ws;
#pragma unroll
            for (int off = 1; off < 32; off <<= 1) {
                int t = __shfl_up_sync(0xffffffffu, ss, off);
                if (lane >= off) ss += t;
            }
            warpsum[lane] = ss - ws;
        }
        __syncthreads();
        int incl = s + warpsum[wid] + carry;
        if (ok) {
            int b0 = incl - v;
            int b1 = b0 + v0, b2 = b1 + v1, b3 = b2 + v2;
            g_rowptr[i0 + 1] = b1; g_rowptr[i0 + 2] = b2;
            g_rowptr[i0 + 3] = b3; g_rowptr[i0 + 4] = b3 + v3;
            int c0 = b0, c1 = b1, c2 = b2, c3 = b3;
#pragma unroll
            for (int p = 0; p < NPART; p++) {
                *(int4*)&g_cur[p * NN + i0] = make_int4(c0, c1, c2, c3);
                c0 += d[p].x; c1 += d[p].y; c2 += d[p].z; c3 += d[p].w;
            }
        }
        __syncthreads();
        if (tid == 1023) carry = incl;
        __syncthreads();
    }
}

// ---------------- fill: 4 edges/thread, no atomics ----------------
__global__ void k_fill(const void* __restrict__ ei) {
    int g = blockIdx.x * blockDim.x + threadIdx.x;   // NE/4 threads
    if (g >= NE / 4) return;
    int is64 = g_is64;
    if (is64 < 0) is64 = detect64((const unsigned int*)ei);
    int e0 = g * 4;
    int src[4], dst[4], rk[4];
    if (is64) {
#pragma unroll
        for (int q = 0; q < 4; q++) {
            src[q] = edge_val(ei, e0 + q, 1);
            dst[q] = edge_val(ei, (long long)NE + e0 + q, 1);
        }
    } else {
        int4 s4 = ((const int4*)ei)[g];
        int4 d4 = ((const int4*)ei)[NE / 4 + g];
        src[0] = s4.x; src[1] = s4.y; src[2] = s4.z; src[3] = s4.w;
        dst[0] = d4.x; dst[1] = d4.y; dst[2] = d4.z; dst[3] = d4.w;
    }
    int4 r4 = ((const int4*)g_rank)[g];
    rk[0] = r4.x; rk[1] = r4.y; rk[2] = r4.z; rk[3] = r4.w;
    int pos[4];
#pragma unroll
    for (int q = 0; q < 4; q++) {
        int part = (e0 + q) & (NPART - 1);
        pos[q] = g_cur[part * NN + dst[q]] + rk[q];
    }
#pragma unroll
    for (int q = 0; q < 4; q++) g_csrc[pos[q]] = src[q];
}

// ---------------- GEMM: 512 threads, 4 row-pairs x 4 cols/thread, f32x2 ----------------
__global__ __launch_bounds__(512, 2) void k_gemm(const float* __restrict__ x,
                                                 const float* __restrict__ W,
                                                 const float* __restrict__ att_src,
                                                 const float* __restrict__ att_dst) {
    __shared__ float xs[32][136];   // [k][row], padded
    __shared__ float ws[32][132];   // [k][col], padded
    int tid = threadIdx.x;
    int lane = tid & 31;
    int row0 = blockIdx.x * 128;
    int r0 = (tid >> 5) * 8;        // 8 rows = 4 pairs per warp
    int c0 = lane * 4;

    unsigned long long acc[4][4];
#pragma unroll
    for (int i = 0; i < 4; i++)
#pragma unroll
        for (int j = 0; j < 4; j++) acc[i][j] = 0ull;

#pragma unroll 1
    for (int kk = 0; kk < 128; kk += 32) {
        {   // W tile: 32 k-rows x 128 cols; 8 floats/thread
            int lk = tid >> 4;
            int lc = (tid & 15) * 8;
            const float4* wp = (const float4*)(W + (size_t)(kk + lk) * 128 + lc);
            float4* q = (float4*)&ws[lk][lc];
            q[0] = wp[0]; q[1] = wp[1];
        }
        {   // x tile: 128 rows x 32 k, transposed; 8 k-values/thread
            int lr = tid >> 2;
            int k0 = (tid & 3) * 8;
            int grow = row0 + lr; if (grow >= NN) grow = NN - 1;
            const float* xp = x + (size_t)grow * 128 + kk + k0;
            float4 a = *(const float4*)xp;
            float4 b = *(const float4*)(xp + 4);
            xs[k0 + 0][lr] = a.x; xs[k0 + 1][lr] = a.y;
            xs[k0 + 2][lr] = a.z; xs[k0 + 3][lr] = a.w;
            xs[k0 + 4][lr] = b.x; xs[k0 + 5][lr] = b.y;
            xs[k0 + 6][lr] = b.z; xs[k0 + 7][lr] = b.w;
        }
        __syncthreads();
#pragma unroll 2
        for (int k = 0; k < 32; k++) {
            ulonglong2 xpA = *(const ulonglong2*)&xs[k][r0];      // pairs 0,1
            ulonglong2 xpB = *(const ulonglong2*)&xs[k][r0 + 4];  // pairs 2,3
            float4 wv = *(const float4*)&ws[k][c0];
            unsigned long long wd0 = pk2(wv.x), wd1 = pk2(wv.y);
            unsigned long long wd2 = pk2(wv.z), wd3 = pk2(wv.w);
            unsigned long long xp[4] = {xpA.x, xpA.y, xpB.x, xpB.y};
#pragma unroll
            for (int i = 0; i < 4; i++) {
                FMA2(acc[i][0], xp[i], wd0, acc[i][0]);
                FMA2(acc[i][1], xp[i], wd1, acc[i][1]);
                FMA2(acc[i][2], xp[i], wd2, acc[i][2]);
                FMA2(acc[i][3], xp[i], wd3, acc[i][3]);
            }
        }
        __syncthreads();
    }

    // epilogue: fp16 xl + attention logits scaled by log2(e)
    float4 asv = ((const float4*)att_src)[lane];
    float4 adv = ((const float4*)att_dst)[lane];
    int head = lane >> 2;
#pragma unroll
    for (int i = 0; i < 4; i++) {
        float a0, b0, a1, b1, a2, b2, a3, b3;   // a*=even row, b*=odd row
        upk2(acc[i][0], a0, b0); upk2(acc[i][1], a1, b1);
        upk2(acc[i][2], a2, b2); upk2(acc[i][3], a3, b3);
#pragma unroll
        for (int par = 0; par < 2; par++) {
            float o0 = par ? b0 : a0, o1 = par ? b1 : a1;
            float o2 = par ? b2 : a2, o3 = par ? b3 : a3;
            int r = row0 + r0 + 2 * i + par;
            float ps = o0 * asv.x + o1 * asv.y + o2 * asv.z + o3 * asv.w;
            float pd = o0 * adv.x + o1 * adv.y + o2 * adv.z + o3 * adv.w;
            ps += __shfl_xor_sync(0xffffffffu, ps, 1);
            ps += __shfl_xor_sync(0xffffffffu, ps, 2);
            pd += __shfl_xor_sync(0xffffffffu, pd, 1);
            pd += __shfl_xor_sync(0xffffffffu, pd, 2);
            if (r < NN) {
                __half2 p0 = __float22half2_rn(make_float2(o0, o1));
                __half2 p1 = __float22half2_rn(make_float2(o2, o3));
                uint2 u;
                u.x = h2bits(p0);
                u.y = h2bits(p1);
                ((uint2*)g_xlh)[(size_t)r * 32 + lane] = u;
                if ((lane & 3) == 0) {
                    g_asrc[r * 8 + head] = ps * LOG2E;
                    g_adst[r * 8 + head] = pd * LOG2E;
                }
            }
        }
    }
}

// ---------------- warp-per-dst aggregation: 2 edges/warp, csrc+asrc prefetch ----------
__global__ __launch_bounds__(256) void k_agg(const float* __restrict__ bias) {
    __shared__ float ss[8][136];
    __shared__ float sq[8][136];
    int g = blockIdx.x * blockDim.x + threadIdx.x;
    int w = g >> 5;
    int lane = g & 31;
    int wid = threadIdx.x >> 5;
    int half = lane >> 4;      // which edge parity this lane serves
    int l = lane & 15;         // position within edge: 8 channels
    int h = l >> 1;            // head of channels 8l..8l+7

    float a0 = 0.f, a1 = 0.f, a2 = 0.f, a3 = 0.f;
    float a4 = 0.f, a5 = 0.f, a6 = 0.f, a7 = 0.f;
    float o0 = 0.f, o1 = 0.f, o2 = 0.f, o3 = 0.f;
    float o4 = 0.f, o5 = 0.f, o6 = 0.f, o7 = 0.f;

    if (w < NN) {
        int start = g_rowptr[w], end = g_rowptr[w + 1];
        float adst = g_adst[w * 8 + h];
        float denom = 0.f;
        const char* xlb = (const char*)g_xlh + (unsigned)(l * 16);  // lane channel base
        const float* asp = g_asrc + h;

        int j = start + half;                       // lane-private edge stream
        int src_n = 0; float e_n = 0.f;
        if (j < end) {
            src_n = __ldg(&g_csrc[j]);
            e_n = __ldg(asp + src_n * 8);
        }
#pragma unroll 2
        while (j < end) {
            int src = src_n;
            float e = e_n + adst;
            int jn = j + 2;
            if (jn < end) {                          // prefetch next edge (index + logit)
                src_n = __ldg(&g_csrc[jn]);
                e_n = __ldg(asp + src_n * 8);
            }
            e = fmaxf(e, 0.2f * e);                  // leaky relu (pre-scaled by log2e)
            float wq = ex2f(e);
            uint4 u = *(const uint4*)(xlb + ((unsigned)src << 8));
            float2 f;
            f = __half22float2(*(__half2*)&u.x);
            a0 = fmaf(wq, f.x, a0); a1 = fmaf(wq, f.y, a1);
            f = __half22float2(*(__half2*)&u.y);
            a2 = fmaf(wq, f.x, a2); a3 = fmaf(wq, f.y, a3);
            f = __half22float2(*(__half2*)&u.z);
            a4 = fmaf(wq, f.x, a4); a5 = fmaf(wq, f.y, a5);
            f = __half22float2(*(__half2*)&u.w);
            a6 = fmaf(wq, f.x, a6); a7 = fmaf(wq, f.y, a7);
            denom += wq;
            j = jn;
        }
        // merge the two edge-parity halves (lane l pairs with lane l+16)
        denom += __shfl_xor_sync(0xffffffffu, denom, 16);
        a0 += __shfl_xor_sync(0xffffffffu, a0, 16);
        a1 += __shfl_xor_sync(0xffffffffu, a1, 16);
        a2 += __shfl_xor_sync(0xffffffffu, a2, 16);
        a3 += __shfl_xor_sync(0xffffffffu, a3, 16);
        a4 += __shfl_xor_sync(0xffffffffu, a4, 16);
        a5 += __shfl_xor_sync(0xffffffffu, a5, 16);
        a6 += __shfl_xor_sync(0xffffffffu, a6, 16);
        a7 += __shfl_xor_sync(0xffffffffu, a7, 16);
        float inv = 1.f / (denom + 1e-16f);
        float4 b0 = ((const float4*)bias)[l * 2];
        float4 b1 = ((const float4*)bias)[l * 2 + 1];
        o0 = fmaf(a0, inv, b0.x); o1 = fmaf(a1, inv, b0.y);
        o2 = fmaf(a2, inv, b0.z); o3 = fmaf(a3, inv, b0.w);
        o4 = fmaf(a4, inv, b1.x); o5 = fmaf(a5, inv, b1.y);
        o6 = fmaf(a6, inv, b1.z); o7 = fmaf(a7, inv, b1.w);
        if (half == 0) {
            // fp16 h store: one STG.128 covers this lane's 8 channels
            uint4 st;
            st.x = h2bits(__float22half2_rn(make_float2(o0, o1)));
            st.y = h2bits(__float22half2_rn(make_float2(o2, o3)));
            st.z = h2bits(__float22half2_rn(make_float2(o4, o5)));
            st.w = h2bits(__float22half2_rn(make_float2(o6, o7)));
            ((uint4*)g_hh)[(size_t)w * 16 + l] = st;
        }
    }

    // fused BN partial stats (fp32 o values): half-0 lanes cover all 128 channels
    if (half == 0) {
        float4 v0 = {o0, o1, o2, o3};
        float4 v1 = {o4, o5, o6, o7};
        float4 q0 = {o0 * o0, o1 * o1, o2 * o2, o3 * o3};
        float4 q1 = {o4 * o4, o5 * o5, o6 * o6, o7 * o7};
        *(float4*)&ss[wid][l * 8] = v0;
        *(float4*)&ss[wid][l * 8 + 4] = v1;
        *(float4*)&sq[wid][l * 8] = q0;
        *(float4*)&sq[wid][l * 8 + 4] = q1;
    }
    __syncthreads();
    int tid = threadIdx.x;
    if (tid < 128) {
        float s = 0.f, q = 0.f;
#pragma unroll
        for (int ww = 0; ww < 8; ww++) { s += ss[ww][tid]; q += sq[ww][tid]; }
        int slot = blockIdx.x & (NSLOT - 1);
        atomicAdd(&g_ps1[slot * 128 + tid], s);
        atomicAdd(&g_ps2[slot * 128 + tid], q);
    }
}

// ---------------- BN params: 1024 threads, parallel slot reduction ----------------
__global__ void k_bnp(const float* __restrict__ gamma,
                      const float* __restrict__ beta) {
    __shared__ float s1[1024], s2[1024];
    int tid = threadIdx.x;
    int c = tid & 127;
    int grp = tid >> 7;                 // 0..7, each covers 8 slots
    float s = 0.f, q = 0.f;
#pragma unroll
    for (int k = 0; k < 8; k++) {
        int slot = grp * 8 + k;
        s += g_ps1[slot * 128 + c];
        q += g_ps2[slot * 128 + c];
    }
    s1[tid] = s; s2[tid] = q;
    __syncthreads();
    if (tid < 128) {
        double S = 0.0, Q = 0.0;
#pragma unroll
        for (int r = 0; r < 8; r++) { S += (double)s1[tid + r * 128]; Q += (double)s2[tid + r * 128]; }
        double mean_d = S / (double)NN;
        double var_d = Q / (double)NN - mean_d * mean_d;
        float sc = gamma[tid] * rsqrtf((float)var_d + 1e-5f);
        g_scale[tid] = sc;
        g_shift[tid] = beta[tid] - (float)mean_d * sc;
    }
}

// ---------------- normalize + ReLU + residual + next-call housekeeping ----------------
__global__ void k_final(const float* __restrict__ x, float* __restrict__ out,
                        const unsigned int* __restrict__ ei) {
    int g = blockIdx.x * blockDim.x + threadIdx.x;   // NN*16 uint4s (8 channels each)
    if (g < NPART * NN) g_deg[g] = 0;
    if (g < NSLOT * 128) { g_ps1[g] = 0.f; g_ps2[g] = 0.f; }
    if (g == 0) g_is64 = detect64(ei);
    if (g >= NN * 16) return;
    int l = g & 15;                                  // channels l*8 .. l*8+7
    uint4 u = ((const uint4*)g_hh)[g];
    float2 f0 = __half22float2(*(__half2*)&u.x);
    float2 f1 = __half22float2(*(__half2*)&u.y);
    float2 f2 = __half22float2(*(__half2*)&u.z);
    float2 f3 = __half22float2(*(__half2*)&u.w);
    float4 xv0 = ((const float4*)x)[g * 2];
    float4 xv1 = ((const float4*)x)[g * 2 + 1];
    float4 sc0 = ((const float4*)g_scale)[l * 2];
    float4 sc1 = ((const float4*)g_scale)[l * 2 + 1];
    float4 sh0 = ((const float4*)g_shift)[l * 2];
    float4 sh1 = ((const float4*)g_shift)[l * 2 + 1];
    float4 o0, o1;
    o0.x = xv0.x + fmaxf(0.f, fmaf(f0.x, sc0.x, sh0.x));
    o0.y = xv0.y + fmaxf(0.f, fmaf(f0.y, sc0.y, sh0.y));
    o0.z = xv0.z + fmaxf(0.f, fmaf(f1.x, sc0.z, sh0.z));
    o0.w = xv0.w + fmaxf(0.f, fmaf(f1.y, sc0.w, sh0.w));
    o1.x = xv1.x + fmaxf(0.f, fmaf(f2.x, sc1.x, sh1.x));
    o1.y = xv1.y + fmaxf(0.f, fmaf(f2.y, sc1.y, sh1.y));
    o1.z = xv1.z + fmaxf(0.f, fmaf(f3.x, sc1.z, sh1.z));
    o1.w = xv1.w + fmaxf(0.f, fmaf(f3.y, sc1.w, sh1.w));
    ((float4*)out)[g * 2] = o0;
    ((float4*)out)[g * 2 + 1] = o1;
}

// ---------------- launch: CSR build forked onto a side stream, overlapped with GEMM --------
extern "C" void kernel_launch(void* const* d_in, const int* in_sizes, int n_in,
                              void* d_out, int out_size) {
    const float* x       = (const float*)d_in[0];
    const void*  ei      = d_in[1];
    const float* W       = (const float*)d_in[2];
    const float* att_src = (const float*)d_in[3];
    const float* att_dst = (const float*)d_in[4];
    const float* bias    = (const float*)d_in[5];
    const float* gamma   = (const float*)d_in[6];
    const float* beta    = (const float*)d_in[7];
    float* out = (float*)d_out;
    (void)in_sizes; (void)n_in; (void)out_size;

    const int WB = (NN * 32 + 255) / 256;     // 6250 (agg)
    const int FB = (NN * 16 + 255) / 256;     // 3125 (final)

    cudaStream_t sB;
    cudaEvent_t eF, eJ;
    cudaStreamCreateWithFlags(&sB, cudaStreamNonBlocking);
    cudaEventCreateWithFlags(&eF, cudaEventDisableTiming);
    cudaEventCreateWithFlags(&eJ, cudaEventDisableTiming);

    cudaEventRecord(eF, 0);                  // fork from the (captured) main stream
    cudaStreamWaitEvent(sB, eF, 0);

    // side stream: CSR build (independent of GEMM)
    k_hist <<<(NE / 2 + 255) / 256, 256, 0, sB>>>(ei);
    k_scan <<<1, 1024, 0, sB>>>();
    k_fill <<<(NE / 4 + 255) / 256, 256, 0, sB>>>(ei);
    cudaEventRecord(eJ, sB);

    // main stream: GEMM concurrently
    k_gemm <<<(NN + 127) / 128, 512>>>(x, W, att_src, att_dst);

    cudaStreamWaitEvent(0, eJ, 0);           // join
    k_agg  <<<WB, 256>>>(bias);
    k_bnp  <<<1, 1024>>>(gamma, beta);
    k_final<<<FB, 256>>>(x, out, (const unsigned int*)ei);
}